// round 9
// baseline (speedup 1.0000x reference)
#include <cuda_runtime.h>
#include <cuda_bf16.h>
#include <math.h>
#include <stdint.h>

// ---------------- problem constants ----------------
constexpr int kB    = 4;
constexpr int kS    = 1000;
constexpr int kHID  = 1024;
constexpr int kNH   = 16;
constexpr int kDK   = 64;
constexpr int kFFH  = 2048;
constexpr int kVOC  = 32000;
constexpr int kROWS = kB * kS;     // 4000
constexpr int kBH   = kB * kNH;    // 64

// ---------------- device scratch (no allocations allowed) ----------------
__device__ float g_pe[kHID];
__device__ float g_x   [kROWS * kHID];
__device__ float g_q   [kBH * kS * kDK];
__device__ float g_k   [kBH * kS * kDK];
__device__ float g_v   [kBH * kS * kDK];
__device__ float g_attn[kROWS * kHID];
__device__ float g_x1  [kROWS * kHID];
__device__ float g_h   [kROWS * kFFH];
__device__ float g_ff  [kROWS * kHID];
__device__ float g_x2  [kROWS * kHID];
__device__ float g_wq  [kHID * kHID];
__device__ float g_wk  [kHID * kHID];
__device__ float g_wv  [kHID * kHID];

// bf16 split pool (164 MB): bhi | blo | ahi | alo
constexpr size_t kOffBhi = 0;
constexpr size_t kOffBlo = (size_t)kHID * kVOC * 2;
constexpr size_t kOffAhi = kOffBlo + (size_t)kHID * kVOC * 2;
constexpr size_t kOffAlo = kOffAhi + (size_t)kROWS * kFFH * 2;
constexpr size_t kPoolSz = kOffAlo + (size_t)kROWS * kFFH * 2;
__device__ __align__(256) char g_pool[kPoolSz];

// ---------------- positional encoding (source-bug constant vector) ----------------
__global__ void pe_kernel() {
    int c = threadIdx.x;                     // 0..1023
    int i = c & ~1;
    double tmp = 999.0 * exp(-(double)i / 1024.0 * log(10000.0));
    g_pe[c] = (c & 1) ? (float)cos(tmp) : (float)sin(tmp);
}

// x[row] = emb[token[row]] + pe
__global__ void embed_kernel(const int* __restrict__ tok, const float* __restrict__ emb) {
    int row = blockIdx.x;
    int t = tok[row];
    const float4* e = (const float4*)(emb + (size_t)t * kHID);
    const float4* p = (const float4*)g_pe;
    float4* xo = (float4*)(g_x + (size_t)row * kHID);
    int c = threadIdx.x;
    float4 a = e[c], b = p[c];
    xo[c] = make_float4(a.x + b.x, a.y + b.y, a.z + b.z, a.w + b.w);
}

// repack W[n][h][d] -> Wp[h][n*64+d]
__global__ void pack_w_kernel(const float* __restrict__ W, float* __restrict__ out) {
    int idx = blockIdx.x * blockDim.x + threadIdx.x;
    if (idx < kHID * kHID) {
        int h = idx >> 10;
        int col = idx & 1023;
        int n = col >> 6, d = col & 63;
        out[idx] = W[((size_t)n * kHID + h) * kDK + d];
    }
}

// ---------------- fp32 -> bf16 hi/lo split (row-major, elementwise, x4) ----------------
__global__ void split4_kernel(const float* __restrict__ in,
                              __nv_bfloat16* __restrict__ hi,
                              __nv_bfloat16* __restrict__ lo, int n4) {
    int i = blockIdx.x * 256 + threadIdx.x;
    if (i >= n4) return;
    float4 x = ((const float4*)in)[i];
    __nv_bfloat16 h0 = __float2bfloat16(x.x), h1 = __float2bfloat16(x.y);
    __nv_bfloat16 h2 = __float2bfloat16(x.z), h3 = __float2bfloat16(x.w);
    __nv_bfloat16 l0 = __float2bfloat16(x.x - __bfloat162float(h0));
    __nv_bfloat16 l1 = __float2bfloat16(x.y - __bfloat162float(h1));
    __nv_bfloat16 l2 = __float2bfloat16(x.z - __bfloat162float(h2));
    __nv_bfloat16 l3 = __float2bfloat16(x.w - __bfloat162float(h3));
    __nv_bfloat162* hp = (__nv_bfloat162*)hi;
    __nv_bfloat162* lp = (__nv_bfloat162*)lo;
    hp[i*2+0] = __nv_bfloat162(h0, h1); hp[i*2+1] = __nv_bfloat162(h2, h3);
    lp[i*2+0] = __nv_bfloat162(l0, l1); lp[i*2+1] = __nv_bfloat162(l2, l3);
}

// ---------------- fp32 [K,N] -> bf16 hi/lo [N,K] (transpose + split) ----------------
__global__ void splitT_kernel(const float* __restrict__ in,
                              __nv_bfloat16* __restrict__ hi,
                              __nv_bfloat16* __restrict__ lo, int K, int N) {
    __shared__ float t[32][33];
    int n0 = blockIdx.x * 32, k0 = blockIdx.y * 32;
    int tx = threadIdx.x;
#pragma unroll
    for (int i = threadIdx.y; i < 32; i += 8)
        t[i][tx] = in[(size_t)(k0 + i) * N + n0 + tx];
    __syncthreads();
#pragma unroll
    for (int i = threadIdx.y; i < 32; i += 8) {
        float x = t[tx][i];
        __nv_bfloat16 h = __float2bfloat16(x);
        size_t o = (size_t)(n0 + i) * K + k0 + tx;
        hi[o] = h;
        lo[o] = __float2bfloat16(x - __bfloat162float(h));
    }
}

// ---------------- cp.async helpers ----------------
__device__ __forceinline__ void cp16(uint32_t dst, const void* src, bool full) {
    int sz = full ? 16 : 0;
    asm volatile("cp.async.cg.shared.global [%0], [%1], 16, %2;"
                 :: "r"(dst), "l"(src), "r"(sz) : "memory");
}
__device__ __forceinline__ void cp_commit() {
    asm volatile("cp.async.commit_group;" ::: "memory");
}

// ---------------- fused bf16-split tensor-core GEMM (single K pass, ldmatrix frags) ----------------
constexpr int kPITCH = 40;
constexpr int kArrSz = 128 * kPITCH;
constexpr int kGemmSmem = 2 * 4 * kArrSz * 2;

template<int EPI>
__global__ __launch_bounds__(256)
void hgemm_fused(const __nv_bfloat16* __restrict__ aHi, const __nv_bfloat16* __restrict__ aLo,
                 const __nv_bfloat16* __restrict__ bHi, const __nv_bfloat16* __restrict__ bLo,
                 const float* __restrict__ bias, float* __restrict__ C,
                 int M, int N, int K) {
    extern __shared__ __align__(16) __nv_bfloat16 dynsm[];
    uint32_t smbase;
    { uint64_t t64; asm("cvta.to.shared.u64 %0, %1;" : "=l"(t64) : "l"(dynsm)); smbase = (uint32_t)t64; }

    int tid = threadIdx.x;
    int wid = tid >> 5, lane = tid & 31;
    int wm = wid >> 2, wn = wid & 3;          // 2x4 warps -> warp tile 64(m) x 32(n)
    int r = lane >> 2, c2 = (lane & 3) * 2;
    int m0 = blockIdx.y * 128, n0 = blockIdx.x * 128;

    const __nv_bfloat16* gsrc[4] = {aHi, aLo, bHi, bLo};

    auto issue_tile = [&](int stage, int k0) {
#pragma unroll
        for (int arr = 0; arr < 4; arr++) {
            const __nv_bfloat16* gp = gsrc[arr];
            bool isA = arr < 2;
#pragma unroll
            for (int i = 0; i < 2; i++) {
                int idx = tid + i * 256;
                int row = idx >> 2;
                int c4 = (idx & 3) * 8;
                int grow = (isA ? m0 : n0) + row;
                bool ok = isA ? (grow < M) : true;
                const void* src = gp + (size_t)(ok ? grow : 0) * K + k0 + c4;
                uint32_t dst = smbase + (uint32_t)(((stage * 4 + arr) * kArrSz + row * kPITCH + c4) * 2);
                cp16(dst, src, ok);
            }
        }
    };

    float acc[4][4][4] = {};

    issue_tile(0, 0);
    cp_commit();

    // ldmatrix per-lane addressing: lane 0-15 -> rows 0-15 at k+0; lane 16-31 -> rows 0-15 at k+8.
    // Matrix order {r0-7/k, r8-15/k, r0-7/k+8, r8-15/k+8}.
    int lrow = lane & 15;
    int lk   = (lane >> 4) << 3;

#define LDSM4(d0,d1,d2,d3,addr) \
    asm volatile("ldmatrix.sync.aligned.m8n8.x4.shared.b16 {%0,%1,%2,%3}, [%4];" \
                 : "=r"(d0), "=r"(d1), "=r"(d2), "=r"(d3) : "r"(addr))

    int stage = 0;
    for (int k0 = 0; k0 < K; k0 += 32) {
        bool hasNext = (k0 + 32) < K;
        if (hasNext) {
            issue_tile(stage ^ 1, k0 + 32);
            cp_commit();
            asm volatile("cp.async.wait_group 1;" ::: "memory");
        } else {
            asm volatile("cp.async.wait_group 0;" ::: "memory");
        }
        __syncthreads();

        uint32_t baseAhi = smbase + (uint32_t)(((stage * 4 + 0) * kArrSz) * 2);
        uint32_t baseAlo = smbase + (uint32_t)(((stage * 4 + 1) * kArrSz) * 2);
        uint32_t baseBhi = smbase + (uint32_t)(((stage * 4 + 2) * kArrSz) * 2);
        uint32_t baseBlo = smbase + (uint32_t)(((stage * 4 + 3) * kArrSz) * 2);

#pragma unroll
        for (int ks = 0; ks < 32; ks += 16) {
            uint32_t ahi[4][4], alo[4][4], bhi[4][2], blo[4][2];
            // A fragments: one x4 per mi per array (m16 x k16)
#pragma unroll
            for (int mi = 0; mi < 4; mi++) {
                uint32_t off = (uint32_t)(((wm * 64 + mi * 16 + lrow) * kPITCH + ks + lk) * 2);
                LDSM4(ahi[mi][0], ahi[mi][1], ahi[mi][2], ahi[mi][3], baseAhi + off);
                LDSM4(alo[mi][0], alo[mi][1], alo[mi][2], alo[mi][3], baseAlo + off);
            }
            // B fragments: one x4 covers two ni (n16 x k16); regs = {b0(ni), b0(ni+1), b1(ni), b1(ni+1)}
#pragma unroll
            for (int p = 0; p < 2; p++) {
                uint32_t off = (uint32_t)(((wn * 32 + p * 16 + lrow) * kPITCH + ks + lk) * 2);
                uint32_t t0h, t1h, t2h, t3h;
                LDSM4(t0h, t1h, t2h, t3h, baseBhi + off);
                bhi[p * 2 + 0][0] = t0h; bhi[p * 2 + 0][1] = t2h;
                bhi[p * 2 + 1][0] = t1h; bhi[p * 2 + 1][1] = t3h;
                uint32_t t0l, t1l, t2l, t3l;
                LDSM4(t0l, t1l, t2l, t3l, baseBlo + off);
                blo[p * 2 + 0][0] = t0l; blo[p * 2 + 0][1] = t2l;
                blo[p * 2 + 1][0] = t1l; blo[p * 2 + 1][1] = t3l;
            }
#define MMA(A0,A1,A2,A3,B0,B1,ACC) \
    asm volatile("mma.sync.aligned.m16n8k16.row.col.f32.bf16.bf16.f32 " \
                 "{%0,%1,%2,%3}, {%4,%5,%6,%7}, {%8,%9}, {%0,%1,%2,%3};" \
                 : "+f"(ACC[0]), "+f"(ACC[1]), "+f"(ACC[2]), "+f"(ACC[3]) \
                 : "r"(A0), "r"(A1), "r"(A2), "r"(A3), "r"(B0), "r"(B1))
#pragma unroll
            for (int mi = 0; mi < 4; mi++)
#pragma unroll
                for (int ni = 0; ni < 4; ni++) {
                    MMA(ahi[mi][0], ahi[mi][1], ahi[mi][2], ahi[mi][3],
                        bhi[ni][0], bhi[ni][1], acc[mi][ni]);
                    MMA(ahi[mi][0], ahi[mi][1], ahi[mi][2], ahi[mi][3],
                        blo[ni][0], blo[ni][1], acc[mi][ni]);
                    MMA(alo[mi][0], alo[mi][1], alo[mi][2], alo[mi][3],
                        bhi[ni][0], bhi[ni][1], acc[mi][ni]);
                }
#undef MMA
        }
        __syncthreads();
        stage ^= 1;
    }
#undef LDSM4

#pragma unroll
    for (int mi = 0; mi < 4; mi++) {
#pragma unroll
        for (int half = 0; half < 2; half++) {
            int row = m0 + wm * 64 + mi * 16 + r + half * 8;
            if (row >= M) continue;
#pragma unroll
            for (int ni = 0; ni < 4; ni++) {
                int col = n0 + wn * 32 + ni * 8 + c2;
                float v0 = acc[mi][ni][half * 2 + 0] + bias[col];
                float v1 = acc[mi][ni][half * 2 + 1] + bias[col + 1];
                if (EPI == 1) { v0 = fmaxf(v0, 0.f); v1 = fmaxf(v1, 0.f); }
                if (EPI == 2) {
                    int b = row / kS, s = row % kS;
                    int n = col >> 6, d = col & 63;
                    size_t base = (((size_t)(b * kNH + n)) * kS + s) * kDK + d;
                    C[base] = v0; C[base + 1] = v1;
                } else {
                    *(float2*)&C[(size_t)row * N + col] = make_float2(v0, v1);
                }
            }
        }
    }
}

// ---------------- fused flash attention ----------------
constexpr int kAttnSmem = 4 * 64 * 68 * 4;

__global__ __launch_bounds__(256)
void flash_attn_kernel() {
    extern __shared__ float asm_[];
    float (*Ks)[68] = (float(*)[68])asm_;                 // [d][s]
    float (*Qs)[68] = (float(*)[68])(asm_ + 64 * 68);     // [d][t]
    float (*Vs)[68] = (float(*)[68])(asm_ + 2 * 64 * 68); // [t][d]
    float (*Ps)[68] = (float(*)[68])(asm_ + 3 * 64 * 68); // [t][s]

    int bh = blockIdx.y;
    int s0 = blockIdx.x * 64;
    const float* kp = g_k + (size_t)bh * kS * kDK;
    const float* qp = g_q + (size_t)bh * kS * kDK;
    const float* vp = g_v + (size_t)bh * kS * kDK;
    int tid = threadIdx.x;
    int tr = tid >> 4, tc = tid & 15;

#pragma unroll
    for (int i = 0; i < 4; i++) {
        int idx = tid + i * 256;
        int r = idx >> 4;
        int c = (idx & 15) << 2;
        float4 vk = (s0 + r < kS) ? *(const float4*)&kp[(size_t)(s0 + r) * kDK + c]
                                  : make_float4(0.f, 0.f, 0.f, 0.f);
        Ks[c + 0][r] = vk.x; Ks[c + 1][r] = vk.y; Ks[c + 2][r] = vk.z; Ks[c + 3][r] = vk.w;
    }

    float m_run[4], l_run[4], acc[4][4];
#pragma unroll
    for (int i = 0; i < 4; i++) {
        m_run[i] = -1e30f; l_run[i] = 0.f;
#pragma unroll
        for (int j = 0; j < 4; j++) acc[i][j] = 0.f;
    }

    for (int t0 = 0; t0 <= s0; t0 += 64) {
        __syncthreads();
#pragma unroll
        for (int i = 0; i < 4; i++) {
            int idx = tid + i * 256;
            int r = idx >> 4;
            int c = (idx & 15) << 2;
            bool ok = (t0 + r < kS);
            float4 vq = ok ? *(const float4*)&qp[(size_t)(t0 + r) * kDK + c]
                           : make_float4(0.f, 0.f, 0.f, 0.f);
            Qs[c + 0][r] = vq.x; Qs[c + 1][r] = vq.y; Qs[c + 2][r] = vq.z; Qs[c + 3][r] = vq.w;
            float4 vv = ok ? *(const float4*)&vp[(size_t)(t0 + r) * kDK + c]
                           : make_float4(0.f, 0.f, 0.f, 0.f);
            *(float4*)&Vs[r][c] = vv;
        }
        __syncthreads();

        float S[4][4] = {};
#pragma unroll
        for (int d = 0; d < 64; d++) {
            float ra[4], rb[4];
#pragma unroll
            for (int i = 0; i < 4; i++) ra[i] = Ks[d][tr * 4 + i];
#pragma unroll
            for (int j = 0; j < 4; j++) rb[j] = Qs[d][tc * 4 + j];
#pragma unroll
            for (int i = 0; i < 4; i++)
#pragma unroll
                for (int j = 0; j < 4; j++) S[i][j] += ra[i] * rb[j];
        }
#pragma unroll
        for (int i = 0; i < 4; i++) {
            int s = s0 + tr * 4 + i;
#pragma unroll
            for (int j = 0; j < 4; j++) {
                int t = t0 + tc * 4 + j;
                S[i][j] = (t > s) ? -INFINITY : floorf(S[i][j] * 0.125f);
            }
        }
        float corr[4];
#pragma unroll
        for (int i = 0; i < 4; i++) {
            float mt = fmaxf(fmaxf(S[i][0], S[i][1]), fmaxf(S[i][2], S[i][3]));
#pragma unroll
            for (int o = 8; o; o >>= 1) mt = fmaxf(mt, __shfl_xor_sync(0xffffffffu, mt, o, 16));
            float nm = fmaxf(m_run[i], mt);
            corr[i] = expf(m_run[i] - nm);
            m_run[i] = nm;
            float ls = 0.f;
#pragma unroll
            for (int j = 0; j < 4; j++) {
                float p = expf(S[i][j] - nm);
                S[i][j] = p;
                ls += p;
            }
#pragma unroll
            for (int o = 8; o; o >>= 1) ls += __shfl_xor_sync(0xffffffffu, ls, o, 16);
            l_run[i] = l_run[i] * corr[i] + ls;
#pragma unroll
            for (int j = 0; j < 4; j++) acc[i][j] *= corr[i];
        }
#pragma unroll
        for (int i = 0; i < 4; i++)
#pragma unroll
            for (int j = 0; j < 4; j++)
                Ps[tc * 4 + j][tr * 4 + i] = S[i][j];
        __syncthreads();

#pragma unroll
        for (int k = 0; k < 64; k++) {
            float ra[4], rb[4];
#pragma unroll
            for (int i = 0; i < 4; i++) ra[i] = Ps[k][tr * 4 + i];
#pragma unroll
            for (int j = 0; j < 4; j++) rb[j] = Vs[k][tc * 4 + j];
#pragma unroll
            for (int i = 0; i < 4; i++)
#pragma unroll
                for (int j = 0; j < 4; j++) acc[i][j] += ra[i] * rb[j];
        }
    }

    int b = bh >> 4, n = bh & 15;
#pragma unroll
    for (int i = 0; i < 4; i++) {
        int s = s0 + tr * 4 + i;
        if (s >= kS) continue;
        float inv = 1.f / l_run[i];
#pragma unroll
        for (int j = 0; j < 4; j++) {
            g_attn[((size_t)(b * kS + s)) * kHID + n * kDK + tc * 4 + j] = acc[i][j] * inv;
        }
    }
}

// ---------------- out = LayerNorm(x + delta) * g + b ----------------
__global__ __launch_bounds__(256)
void add_ln_kernel(const float* __restrict__ xin, const float* __restrict__ dl,
                   const float* __restrict__ g, const float* __restrict__ b,
                   float* __restrict__ out) {
    int row = blockIdx.x;
    int tid = threadIdx.x;
    const float* xr = xin + (size_t)row * kHID;
    const float* dr = dl  + (size_t)row * kHID;
    __shared__ float red[256];

    float v[4]; float ls = 0.f;
#pragma unroll
    for (int i = 0; i < 4; i++) { int c = tid + i * 256; v[i] = xr[c] + dr[c]; ls += v[i]; }
    red[tid] = ls; __syncthreads();
    for (int o = 128; o; o >>= 1) { if (tid < o) red[tid] += red[tid + o]; __syncthreads(); }
    float mu = red[0] * (1.f / kHID);
    __syncthreads();

    float lv = 0.f;
#pragma unroll
    for (int i = 0; i < 4; i++) { float d = v[i] - mu; lv += d * d; }
    red[tid] = lv; __syncthreads();
    for (int o = 128; o; o >>= 1) { if (tid < o) red[tid] += red[tid + o]; __syncthreads(); }
    float rstd = 1.f / sqrtf(red[0] * (1.f / kHID) + 1e-5f);

    float* orow = out + (size_t)row * kHID;
#pragma unroll
    for (int i = 0; i < 4; i++) {
        int c = tid + i * 256;
        orow[c] = (v[i] - mu) * rstd * g[c] + b[c];
    }
}

// ---------------- launcher ----------------
extern "C" void kernel_launch(void* const* d_in, const int* in_sizes, int n_in,
                              void* d_out, int out_size) {
    const int*   tok  = (const int*)  d_in[0];
    const float* emb  = (const float*)d_in[1];
    const float* Wq   = (const float*)d_in[2];
    const float* bq   = (const float*)d_in[3];
    const float* Wk   = (const float*)d_in[4];
    const float* bk   = (const float*)d_in[5];
    const float* Wv   = (const float*)d_in[6];
    const float* bv   = (const float*)d_in[7];
    const float* Wc   = (const float*)d_in[8];
    const float* bc   = (const float*)d_in[9];
    const float* ln1g = (const float*)d_in[10];
    const float* ln1b = (const float*)d_in[11];
    const float* W1   = (const float*)d_in[12];
    const float* b1   = (const float*)d_in[13];
    const float* W2   = (const float*)d_in[14];
    const float* b2   = (const float*)d_in[15];
    const float* ln2g = (const float*)d_in[16];
    const float* ln2b = (const float*)d_in[17];
    const float* Wlog = (const float*)d_in[18];
    const float* blog = (const float*)d_in[19];
    float* out = (float*)d_out;

    float *px, *pq, *pk, *pv, *pattn, *px1, *ph, *pff, *px2, *pwq, *pwk, *pwv;
    char* ppool;
    cudaGetSymbolAddress((void**)&px,    g_x);
    cudaGetSymbolAddress((void**)&pq,    g_q);
    cudaGetSymbolAddress((void**)&pk,    g_k);
    cudaGetSymbolAddress((void**)&pv,    g_v);
    cudaGetSymbolAddress((void**)&pattn, g_attn);
    cudaGetSymbolAddress((void**)&px1,   g_x1);
    cudaGetSymbolAddress((void**)&ph,    g_h);
    cudaGetSymbolAddress((void**)&pff,   g_ff);
    cudaGetSymbolAddress((void**)&px2,   g_x2);
    cudaGetSymbolAddress((void**)&pwq,   g_wq);
    cudaGetSymbolAddress((void**)&pwk,   g_wk);
    cudaGetSymbolAddress((void**)&pwv,   g_wv);
    cudaGetSymbolAddress((void**)&ppool, g_pool);

    __nv_bfloat16* pbhi = (__nv_bfloat16*)(ppool + kOffBhi);
    __nv_bfloat16* pblo = (__nv_bfloat16*)(ppool + kOffBlo);
    __nv_bfloat16* pahi = (__nv_bfloat16*)(ppool + kOffAhi);
    __nv_bfloat16* palo = (__nv_bfloat16*)(ppool + kOffAlo);

    cudaFuncSetAttribute(hgemm_fused<0>, cudaFuncAttributeMaxDynamicSharedMemorySize, kGemmSmem);
    cudaFuncSetAttribute(hgemm_fused<1>, cudaFuncAttributeMaxDynamicSharedMemorySize, kGemmSmem);
    cudaFuncSetAttribute(hgemm_fused<2>, cudaFuncAttributeMaxDynamicSharedMemorySize, kGemmSmem);
    cudaFuncSetAttribute(flash_attn_kernel, cudaFuncAttributeMaxDynamicSharedMemorySize, kAttnSmem);

    dim3 t328(32, 8);

    // 1. positional encoding + embedding
    pe_kernel<<<1, 1024>>>();
    embed_kernel<<<kROWS, 256>>>(tok, emb);

    // 2. repack per-head QKV weights into [HID, HID] fp32
    pack_w_kernel<<<(kHID * kHID + 255) / 256, 256>>>(Wq, pwq);
    pack_w_kernel<<<(kHID * kHID + 255) / 256, 256>>>(Wk, pwk);
    pack_w_kernel<<<(kHID * kHID + 255) / 256, 256>>>(Wv, pwv);

    // 3. QKV projections on tensor cores (fused hi/lo split), scatter epilogue
    split4_kernel<<<(kROWS * kHID / 4 + 255) / 256, 256>>>(px, pahi, palo, kROWS * kHID / 4);
    dim3 gQ(kHID / 128, (kROWS + 127) / 128);
    splitT_kernel<<<dim3(kHID / 32, kHID / 32), t328>>>(pwq, pbhi, pblo, kHID, kHID);
    hgemm_fused<2><<<gQ, 256, kGemmSmem>>>(pahi, palo, pbhi, pblo, bq, pq, kROWS, kHID, kHID);
    splitT_kernel<<<dim3(kHID / 32, kHID / 32), t328>>>(pwk, pbhi, pblo, kHID, kHID);
    hgemm_fused<2><<<gQ, 256, kGemmSmem>>>(pahi, palo, pbhi, pblo, bk, pk, kROWS, kHID, kHID);
    splitT_kernel<<<dim3(kHID / 32, kHID / 32), t328>>>(pwv, pbhi, pblo, kHID, kHID);
    hgemm_fused<2><<<gQ, 256, kGemmSmem>>>(pahi, palo, pbhi, pblo, bv, pv, kROWS, kHID, kHID);

    // 4. fused flash attention (fp32 — protects floor() discontinuity)
    flash_attn_kernel<<<dim3(16, kBH), 256, kAttnSmem>>>();

    // 5. output projection + residual + LN1
    split4_kernel<<<(kROWS * kHID / 4 + 255) / 256, 256>>>(pattn, pahi, palo, kROWS * kHID / 4);
    splitT_kernel<<<dim3(kHID / 32, kHID / 32), t328>>>(Wc, pbhi, pblo, kHID, kHID);
    hgemm_fused<0><<<dim3(kHID / 128, (kROWS + 127) / 128), 256, kGemmSmem>>>(pahi, palo, pbhi, pblo, bc, pff, kROWS, kHID, kHID);
    add_ln_kernel<<<kROWS, 256>>>(px, pff, ln1g, ln1b, px1);

    // 6. feed-forward + residual + LN2
    split4_kernel<<<(kROWS * kHID / 4 + 255) / 256, 256>>>(px1, pahi, palo, kROWS * kHID / 4);
    splitT_kernel<<<dim3(kFFH / 32, kHID / 32), t328>>>(W1, pbhi, pblo, kHID, kFFH);
    hgemm_fused<1><<<dim3(kFFH / 128, (kROWS + 127) / 128), 256, kGemmSmem>>>(pahi, palo, pbhi, pblo, b1, ph, kROWS, kFFH, kHID);
    split4_kernel<<<(kROWS * kFFH / 4 + 255) / 256, 256>>>(ph, pahi, palo, kROWS * kFFH / 4);
    splitT_kernel<<<dim3(kHID / 32, kFFH / 32), t328>>>(W2, pbhi, pblo, kFFH, kHID);
    hgemm_fused<0><<<dim3(kHID / 128, (kROWS + 127) / 128), 256, kGemmSmem>>>(pahi, palo, pbhi, pblo, b2, pff, kROWS, kHID, kFFH);
    add_ln_kernel<<<kROWS, 256>>>(px1, pff, ln2g, ln2b, px2);

    // 7. logits (dominant GEMM) on tensor cores -> d_out
    split4_kernel<<<(kROWS * kHID / 4 + 255) / 256, 256>>>(px2, pahi, palo, kROWS * kHID / 4);
    splitT_kernel<<<dim3(kVOC / 32, kHID / 32), t328>>>(Wlog, pbhi, pblo, kHID, kVOC);
    hgemm_fused<0><<<dim3(kVOC / 128, (kROWS + 127) / 128), 256, kGemmSmem>>>(pahi, palo, pbhi, pblo, blog, out, kROWS, kVOC, kHID);

    (void)in_sizes; (void)n_in; (void)out_size;
}

// round 10
// speedup vs baseline: 1.0930x; 1.0930x over previous
#include <cuda_runtime.h>
#include <cuda_bf16.h>
#include <math.h>
#include <stdint.h>

// ---------------- problem constants ----------------
constexpr int kB    = 4;
constexpr int kS    = 1000;
constexpr int kHID  = 1024;
constexpr int kNH   = 16;
constexpr int kDK   = 64;
constexpr int kFFH  = 2048;
constexpr int kVOC  = 32000;
constexpr int kROWS = kB * kS;     // 4000
constexpr int kBH   = kB * kNH;    // 64

// ---------------- device scratch (no allocations allowed) ----------------
__device__ float g_pe[kHID];
__device__ float g_x   [kROWS * kHID];
__device__ float g_q   [kBH * kS * kDK];
__device__ float g_k   [kBH * kS * kDK];
__device__ float g_v   [kBH * kS * kDK];
__device__ float g_attn[kROWS * kHID];
__device__ float g_x1  [kROWS * kHID];
__device__ float g_h   [kROWS * kFFH];
__device__ float g_ff  [kROWS * kHID];
__device__ float g_x2  [kROWS * kHID];
__device__ float g_wq  [kHID * kHID];
__device__ float g_wk  [kHID * kHID];
__device__ float g_wv  [kHID * kHID];

// bf16 split pool (164 MB): bhi | blo | ahi | alo
constexpr size_t kOffBhi = 0;
constexpr size_t kOffBlo = (size_t)kHID * kVOC * 2;
constexpr size_t kOffAhi = kOffBlo + (size_t)kHID * kVOC * 2;
constexpr size_t kOffAlo = kOffAhi + (size_t)kROWS * kFFH * 2;
constexpr size_t kPoolSz = kOffAlo + (size_t)kROWS * kFFH * 2;
__device__ __align__(256) char g_pool[kPoolSz];

// ---------------- positional encoding (source-bug constant vector) ----------------
__global__ void pe_kernel() {
    int c = threadIdx.x;                     // 0..1023
    int i = c & ~1;
    double tmp = 999.0 * exp(-(double)i / 1024.0 * log(10000.0));
    g_pe[c] = (c & 1) ? (float)cos(tmp) : (float)sin(tmp);
}

// x[row] = emb[token[row]] + pe
__global__ void embed_kernel(const int* __restrict__ tok, const float* __restrict__ emb) {
    int row = blockIdx.x;
    int t = tok[row];
    const float4* e = (const float4*)(emb + (size_t)t * kHID);
    const float4* p = (const float4*)g_pe;
    float4* xo = (float4*)(g_x + (size_t)row * kHID);
    int c = threadIdx.x;
    float4 a = e[c], b = p[c];
    xo[c] = make_float4(a.x + b.x, a.y + b.y, a.z + b.z, a.w + b.w);
}

// repack W[n][h][d] -> Wp[h][n*64+d]
__global__ void pack_w_kernel(const float* __restrict__ W, float* __restrict__ out) {
    int idx = blockIdx.x * blockDim.x + threadIdx.x;
    if (idx < kHID * kHID) {
        int h = idx >> 10;
        int col = idx & 1023;
        int n = col >> 6, d = col & 63;
        out[idx] = W[((size_t)n * kHID + h) * kDK + d];
    }
}

// ---------------- fp32 -> bf16 hi/lo split (row-major, elementwise, x4) ----------------
__global__ void split4_kernel(const float* __restrict__ in,
                              __nv_bfloat16* __restrict__ hi,
                              __nv_bfloat16* __restrict__ lo, int n4) {
    int i = blockIdx.x * 256 + threadIdx.x;
    if (i >= n4) return;
    float4 x = ((const float4*)in)[i];
    __nv_bfloat16 h0 = __float2bfloat16(x.x), h1 = __float2bfloat16(x.y);
    __nv_bfloat16 h2 = __float2bfloat16(x.z), h3 = __float2bfloat16(x.w);
    __nv_bfloat16 l0 = __float2bfloat16(x.x - __bfloat162float(h0));
    __nv_bfloat16 l1 = __float2bfloat16(x.y - __bfloat162float(h1));
    __nv_bfloat16 l2 = __float2bfloat16(x.z - __bfloat162float(h2));
    __nv_bfloat16 l3 = __float2bfloat16(x.w - __bfloat162float(h3));
    __nv_bfloat162* hp = (__nv_bfloat162*)hi;
    __nv_bfloat162* lp = (__nv_bfloat162*)lo;
    hp[i*2+0] = __nv_bfloat162(h0, h1); hp[i*2+1] = __nv_bfloat162(h2, h3);
    lp[i*2+0] = __nv_bfloat162(l0, l1); lp[i*2+1] = __nv_bfloat162(l2, l3);
}

// ---------------- fp32 [K,N] -> bf16 hi/lo [N,K] (transpose + split) ----------------
__global__ void splitT_kernel(const float* __restrict__ in,
                              __nv_bfloat16* __restrict__ hi,
                              __nv_bfloat16* __restrict__ lo, int K, int N) {
    __shared__ float t[32][33];
    int n0 = blockIdx.x * 32, k0 = blockIdx.y * 32;
    int tx = threadIdx.x;
#pragma unroll
    for (int i = threadIdx.y; i < 32; i += 8)
        t[i][tx] = in[(size_t)(k0 + i) * N + n0 + tx];
    __syncthreads();
#pragma unroll
    for (int i = threadIdx.y; i < 32; i += 8) {
        float x = t[tx][i];
        __nv_bfloat16 h = __float2bfloat16(x);
        size_t o = (size_t)(n0 + i) * K + k0 + tx;
        hi[o] = h;
        lo[o] = __float2bfloat16(x - __bfloat162float(h));
    }
}

// ---------------- cp.async helpers ----------------
__device__ __forceinline__ void cp16(uint32_t dst, const void* src, bool full) {
    int sz = full ? 16 : 0;
    asm volatile("cp.async.cg.shared.global [%0], [%1], 16, %2;"
                 :: "r"(dst), "l"(src), "r"(sz) : "memory");
}
__device__ __forceinline__ void cp_commit() {
    asm volatile("cp.async.commit_group;" ::: "memory");
}

// ---------------- fused bf16-split tensor-core GEMM (single K pass, 3 MMAs/tile) ----------------
// Grid mapping: blockIdx.x = M-tile (fast), blockIdx.y = N-tile — a wave covers all
// M-tiles for a few N-groups, so each B tile is DRAM-fetched once and L2-served.
constexpr int kPITCH = 40;
constexpr int kArrSz = 128 * kPITCH;
constexpr int kGemmSmem = 2 * 4 * kArrSz * 2;

template<int EPI>
__global__ __launch_bounds__(256)
void hgemm_fused(const __nv_bfloat16* __restrict__ aHi, const __nv_bfloat16* __restrict__ aLo,
                 const __nv_bfloat16* __restrict__ bHi, const __nv_bfloat16* __restrict__ bLo,
                 const float* __restrict__ bias, float* __restrict__ C,
                 int M, int N, int K) {
    extern __shared__ __align__(16) __nv_bfloat16 dynsm[];
    uint32_t smbase;
    { uint64_t t64; asm("cvta.to.shared.u64 %0, %1;" : "=l"(t64) : "l"(dynsm)); smbase = (uint32_t)t64; }

    int tid = threadIdx.x;
    int wid = tid >> 5, lane = tid & 31;
    int wm = wid >> 2, wn = wid & 3;          // 2x4 warps -> warp tile 64(m) x 32(n)
    int r = lane >> 2, c2 = (lane & 3) * 2;
    int m0 = blockIdx.x * 128, n0 = blockIdx.y * 128;   // m fast -> B-tile L2 reuse

    const __nv_bfloat16* gsrc[4] = {aHi, aLo, bHi, bLo};

    auto issue_tile = [&](int stage, int k0) {
#pragma unroll
        for (int arr = 0; arr < 4; arr++) {
            const __nv_bfloat16* gp = gsrc[arr];
            bool isA = arr < 2;
#pragma unroll
            for (int i = 0; i < 2; i++) {
                int idx = tid + i * 256;
                int row = idx >> 2;
                int c4 = (idx & 3) * 8;
                int grow = (isA ? m0 : n0) + row;
                bool ok = isA ? (grow < M) : true;
                const void* src = gp + (size_t)(ok ? grow : 0) * K + k0 + c4;
                uint32_t dst = smbase + (uint32_t)(((stage * 4 + arr) * kArrSz + row * kPITCH + c4) * 2);
                cp16(dst, src, ok);
            }
        }
    };

    float acc[4][4][4] = {};

    issue_tile(0, 0);
    cp_commit();

    int stage = 0;
    for (int k0 = 0; k0 < K; k0 += 32) {
        bool hasNext = (k0 + 32) < K;
        if (hasNext) {
            issue_tile(stage ^ 1, k0 + 32);
            cp_commit();
            asm volatile("cp.async.wait_group 1;" ::: "memory");
        } else {
            asm volatile("cp.async.wait_group 0;" ::: "memory");
        }
        __syncthreads();

        const __nv_bfloat16* sAhi = dynsm + (stage * 4 + 0) * kArrSz;
        const __nv_bfloat16* sAlo = dynsm + (stage * 4 + 1) * kArrSz;
        const __nv_bfloat16* sBhi = dynsm + (stage * 4 + 2) * kArrSz;
        const __nv_bfloat16* sBlo = dynsm + (stage * 4 + 3) * kArrSz;

#pragma unroll
        for (int ks = 0; ks < 32; ks += 16) {
            uint32_t ahi[4][4], alo[4][4], bhi[4][2], blo[4][2];
#pragma unroll
            for (int mi = 0; mi < 4; mi++) {
                int rr = (wm * 64 + mi * 16 + r) * kPITCH + ks + c2;
                ahi[mi][0] = *(const uint32_t*)&sAhi[rr];
                ahi[mi][1] = *(const uint32_t*)&sAhi[rr + 8 * kPITCH];
                ahi[mi][2] = *(const uint32_t*)&sAhi[rr + 8];
                ahi[mi][3] = *(const uint32_t*)&sAhi[rr + 8 * kPITCH + 8];
                alo[mi][0] = *(const uint32_t*)&sAlo[rr];
                alo[mi][1] = *(const uint32_t*)&sAlo[rr + 8 * kPITCH];
                alo[mi][2] = *(const uint32_t*)&sAlo[rr + 8];
                alo[mi][3] = *(const uint32_t*)&sAlo[rr + 8 * kPITCH + 8];
            }
#pragma unroll
            for (int ni = 0; ni < 4; ni++) {
                int rr = (wn * 32 + ni * 8 + r) * kPITCH + ks + c2;
                bhi[ni][0] = *(const uint32_t*)&sBhi[rr];
                bhi[ni][1] = *(const uint32_t*)&sBhi[rr + 8];
                blo[ni][0] = *(const uint32_t*)&sBlo[rr];
                blo[ni][1] = *(const uint32_t*)&sBlo[rr + 8];
            }
#define MMA(A0,A1,A2,A3,B0,B1,ACC) \
    asm volatile("mma.sync.aligned.m16n8k16.row.col.f32.bf16.bf16.f32 " \
                 "{%0,%1,%2,%3}, {%4,%5,%6,%7}, {%8,%9}, {%0,%1,%2,%3};" \
                 : "+f"(ACC[0]), "+f"(ACC[1]), "+f"(ACC[2]), "+f"(ACC[3]) \
                 : "r"(A0), "r"(A1), "r"(A2), "r"(A3), "r"(B0), "r"(B1))
#pragma unroll
            for (int mi = 0; mi < 4; mi++)
#pragma unroll
                for (int ni = 0; ni < 4; ni++) {
                    MMA(ahi[mi][0], ahi[mi][1], ahi[mi][2], ahi[mi][3],
                        bhi[ni][0], bhi[ni][1], acc[mi][ni]);
                    MMA(ahi[mi][0], ahi[mi][1], ahi[mi][2], ahi[mi][3],
                        blo[ni][0], blo[ni][1], acc[mi][ni]);
                    MMA(alo[mi][0], alo[mi][1], alo[mi][2], alo[mi][3],
                        bhi[ni][0], bhi[ni][1], acc[mi][ni]);
                }
#undef MMA
        }
        __syncthreads();
        stage ^= 1;
    }

#pragma unroll
    for (int mi = 0; mi < 4; mi++) {
#pragma unroll
        for (int half = 0; half < 2; half++) {
            int row = m0 + wm * 64 + mi * 16 + r + half * 8;
            if (row >= M) continue;
#pragma unroll
            for (int ni = 0; ni < 4; ni++) {
                int col = n0 + wn * 32 + ni * 8 + c2;
                float v0 = acc[mi][ni][half * 2 + 0] + bias[col];
                float v1 = acc[mi][ni][half * 2 + 1] + bias[col + 1];
                if (EPI == 1) { v0 = fmaxf(v0, 0.f); v1 = fmaxf(v1, 0.f); }
                if (EPI == 2) {
                    int b = row / kS, s = row % kS;
                    int n = col >> 6, d = col & 63;
                    size_t base = (((size_t)(b * kNH + n)) * kS + s) * kDK + d;
                    C[base] = v0; C[base + 1] = v1;
                } else {
                    *(float2*)&C[(size_t)row * N + col] = make_float2(v0, v1);
                }
            }
        }
    }
}

// ---------------- fused flash attention ----------------
constexpr int kAttnSmem = 4 * 64 * 68 * 4;

__global__ __launch_bounds__(256)
void flash_attn_kernel() {
    extern __shared__ float asm_[];
    float (*Ks)[68] = (float(*)[68])asm_;                 // [d][s]
    float (*Qs)[68] = (float(*)[68])(asm_ + 64 * 68);     // [d][t]
    float (*Vs)[68] = (float(*)[68])(asm_ + 2 * 64 * 68); // [t][d]
    float (*Ps)[68] = (float(*)[68])(asm_ + 3 * 64 * 68); // [t][s]

    int bh = blockIdx.y;
    int s0 = blockIdx.x * 64;
    const float* kp = g_k + (size_t)bh * kS * kDK;
    const float* qp = g_q + (size_t)bh * kS * kDK;
    const float* vp = g_v + (size_t)bh * kS * kDK;
    int tid = threadIdx.x;
    int tr = tid >> 4, tc = tid & 15;

#pragma unroll
    for (int i = 0; i < 4; i++) {
        int idx = tid + i * 256;
        int r = idx >> 4;
        int c = (idx & 15) << 2;
        float4 vk = (s0 + r < kS) ? *(const float4*)&kp[(size_t)(s0 + r) * kDK + c]
                                  : make_float4(0.f, 0.f, 0.f, 0.f);
        Ks[c + 0][r] = vk.x; Ks[c + 1][r] = vk.y; Ks[c + 2][r] = vk.z; Ks[c + 3][r] = vk.w;
    }

    float m_run[4], l_run[4], acc[4][4];
#pragma unroll
    for (int i = 0; i < 4; i++) {
        m_run[i] = -1e30f; l_run[i] = 0.f;
#pragma unroll
        for (int j = 0; j < 4; j++) acc[i][j] = 0.f;
    }

    for (int t0 = 0; t0 <= s0; t0 += 64) {
        __syncthreads();
#pragma unroll
        for (int i = 0; i < 4; i++) {
            int idx = tid + i * 256;
            int r = idx >> 4;
            int c = (idx & 15) << 2;
            bool ok = (t0 + r < kS);
            float4 vq = ok ? *(const float4*)&qp[(size_t)(t0 + r) * kDK + c]
                           : make_float4(0.f, 0.f, 0.f, 0.f);
            Qs[c + 0][r] = vq.x; Qs[c + 1][r] = vq.y; Qs[c + 2][r] = vq.z; Qs[c + 3][r] = vq.w;
            float4 vv = ok ? *(const float4*)&vp[(size_t)(t0 + r) * kDK + c]
                           : make_float4(0.f, 0.f, 0.f, 0.f);
            *(float4*)&Vs[r][c] = vv;
        }
        __syncthreads();

        float S[4][4] = {};
#pragma unroll
        for (int d = 0; d < 64; d++) {
            float ra[4], rb[4];
#pragma unroll
            for (int i = 0; i < 4; i++) ra[i] = Ks[d][tr * 4 + i];
#pragma unroll
            for (int j = 0; j < 4; j++) rb[j] = Qs[d][tc * 4 + j];
#pragma unroll
            for (int i = 0; i < 4; i++)
#pragma unroll
                for (int j = 0; j < 4; j++) S[i][j] += ra[i] * rb[j];
        }
#pragma unroll
        for (int i = 0; i < 4; i++) {
            int s = s0 + tr * 4 + i;
#pragma unroll
            for (int j = 0; j < 4; j++) {
                int t = t0 + tc * 4 + j;
                S[i][j] = (t > s) ? -INFINITY : floorf(S[i][j] * 0.125f);
            }
        }
        float corr[4];
#pragma unroll
        for (int i = 0; i < 4; i++) {
            float mt = fmaxf(fmaxf(S[i][0], S[i][1]), fmaxf(S[i][2], S[i][3]));
#pragma unroll
            for (int o = 8; o; o >>= 1) mt = fmaxf(mt, __shfl_xor_sync(0xffffffffu, mt, o, 16));
            float nm = fmaxf(m_run[i], mt);
            corr[i] = expf(m_run[i] - nm);
            m_run[i] = nm;
            float ls = 0.f;
#pragma unroll
            for (int j = 0; j < 4; j++) {
                float p = expf(S[i][j] - nm);
                S[i][j] = p;
                ls += p;
            }
#pragma unroll
            for (int o = 8; o; o >>= 1) ls += __shfl_xor_sync(0xffffffffu, ls, o, 16);
            l_run[i] = l_run[i] * corr[i] + ls;
#pragma unroll
            for (int j = 0; j < 4; j++) acc[i][j] *= corr[i];
        }
#pragma unroll
        for (int i = 0; i < 4; i++)
#pragma unroll
            for (int j = 0; j < 4; j++)
                Ps[tc * 4 + j][tr * 4 + i] = S[i][j];
        __syncthreads();

#pragma unroll
        for (int k = 0; k < 64; k++) {
            float ra[4], rb[4];
#pragma unroll
            for (int i = 0; i < 4; i++) ra[i] = Ps[k][tr * 4 + i];
#pragma unroll
            for (int j = 0; j < 4; j++) rb[j] = Vs[k][tc * 4 + j];
#pragma unroll
            for (int i = 0; i < 4; i++)
#pragma unroll
                for (int j = 0; j < 4; j++) acc[i][j] += ra[i] * rb[j];
        }
    }

    int b = bh >> 4, n = bh & 15;
#pragma unroll
    for (int i = 0; i < 4; i++) {
        int s = s0 + tr * 4 + i;
        if (s >= kS) continue;
        float inv = 1.f / l_run[i];
#pragma unroll
        for (int j = 0; j < 4; j++) {
            g_attn[((size_t)(b * kS + s)) * kHID + n * kDK + tc * 4 + j] = acc[i][j] * inv;
        }
    }
}

// ---------------- out = LayerNorm(x + delta) * g + b ----------------
__global__ __launch_bounds__(256)
void add_ln_kernel(const float* __restrict__ xin, const float* __restrict__ dl,
                   const float* __restrict__ g, const float* __restrict__ b,
                   float* __restrict__ out) {
    int row = blockIdx.x;
    int tid = threadIdx.x;
    const float* xr = xin + (size_t)row * kHID;
    const float* dr = dl  + (size_t)row * kHID;
    __shared__ float red[256];

    float v[4]; float ls = 0.f;
#pragma unroll
    for (int i = 0; i < 4; i++) { int c = tid + i * 256; v[i] = xr[c] + dr[c]; ls += v[i]; }
    red[tid] = ls; __syncthreads();
    for (int o = 128; o; o >>= 1) { if (tid < o) red[tid] += red[tid + o]; __syncthreads(); }
    float mu = red[0] * (1.f / kHID);
    __syncthreads();

    float lv = 0.f;
#pragma unroll
    for (int i = 0; i < 4; i++) { float d = v[i] - mu; lv += d * d; }
    red[tid] = lv; __syncthreads();
    for (int o = 128; o; o >>= 1) { if (tid < o) red[tid] += red[tid + o]; __syncthreads(); }
    float rstd = 1.f / sqrtf(red[0] * (1.f / kHID) + 1e-5f);

    float* orow = out + (size_t)row * kHID;
#pragma unroll
    for (int i = 0; i < 4; i++) {
        int c = tid + i * 256;
        orow[c] = (v[i] - mu) * rstd * g[c] + b[c];
    }
}

// ---------------- launcher ----------------
extern "C" void kernel_launch(void* const* d_in, const int* in_sizes, int n_in,
                              void* d_out, int out_size) {
    const int*   tok  = (const int*)  d_in[0];
    const float* emb  = (const float*)d_in[1];
    const float* Wq   = (const float*)d_in[2];
    const float* bq   = (const float*)d_in[3];
    const float* Wk   = (const float*)d_in[4];
    const float* bk   = (const float*)d_in[5];
    const float* Wv   = (const float*)d_in[6];
    const float* bv   = (const float*)d_in[7];
    const float* Wc   = (const float*)d_in[8];
    const float* bc   = (const float*)d_in[9];
    const float* ln1g = (const float*)d_in[10];
    const float* ln1b = (const float*)d_in[11];
    const float* W1   = (const float*)d_in[12];
    const float* b1   = (const float*)d_in[13];
    const float* W2   = (const float*)d_in[14];
    const float* b2   = (const float*)d_in[15];
    const float* ln2g = (const float*)d_in[16];
    const float* ln2b = (const float*)d_in[17];
    const float* Wlog = (const float*)d_in[18];
    const float* blog = (const float*)d_in[19];
    float* out = (float*)d_out;

    float *px, *pq, *pk, *pv, *pattn, *px1, *ph, *pff, *px2, *pwq, *pwk, *pwv;
    char* ppool;
    cudaGetSymbolAddress((void**)&px,    g_x);
    cudaGetSymbolAddress((void**)&pq,    g_q);
    cudaGetSymbolAddress((void**)&pk,    g_k);
    cudaGetSymbolAddress((void**)&pv,    g_v);
    cudaGetSymbolAddress((void**)&pattn, g_attn);
    cudaGetSymbolAddress((void**)&px1,   g_x1);
    cudaGetSymbolAddress((void**)&ph,    g_h);
    cudaGetSymbolAddress((void**)&pff,   g_ff);
    cudaGetSymbolAddress((void**)&px2,   g_x2);
    cudaGetSymbolAddress((void**)&pwq,   g_wq);
    cudaGetSymbolAddress((void**)&pwk,   g_wk);
    cudaGetSymbolAddress((void**)&pwv,   g_wv);
    cudaGetSymbolAddress((void**)&ppool, g_pool);

    __nv_bfloat16* pbhi = (__nv_bfloat16*)(ppool + kOffBhi);
    __nv_bfloat16* pblo = (__nv_bfloat16*)(ppool + kOffBlo);
    __nv_bfloat16* pahi = (__nv_bfloat16*)(ppool + kOffAhi);
    __nv_bfloat16* palo = (__nv_bfloat16*)(ppool + kOffAlo);

    cudaFuncSetAttribute(hgemm_fused<0>, cudaFuncAttributeMaxDynamicSharedMemorySize, kGemmSmem);
    cudaFuncSetAttribute(hgemm_fused<1>, cudaFuncAttributeMaxDynamicSharedMemorySize, kGemmSmem);
    cudaFuncSetAttribute(hgemm_fused<2>, cudaFuncAttributeMaxDynamicSharedMemorySize, kGemmSmem);
    cudaFuncSetAttribute(flash_attn_kernel, cudaFuncAttributeMaxDynamicSharedMemorySize, kAttnSmem);

    dim3 t328(32, 8);
    constexpr int kMB = (kROWS + 127) / 128;   // 32 m-blocks

    // 1. positional encoding + embedding
    pe_kernel<<<1, 1024>>>();
    embed_kernel<<<kROWS, 256>>>(tok, emb);

    // 2. repack per-head QKV weights into [HID, HID] fp32
    pack_w_kernel<<<(kHID * kHID + 255) / 256, 256>>>(Wq, pwq);
    pack_w_kernel<<<(kHID * kHID + 255) / 256, 256>>>(Wk, pwk);
    pack_w_kernel<<<(kHID * kHID + 255) / 256, 256>>>(Wv, pwv);

    // 3. QKV projections on tensor cores (fused hi/lo split), scatter epilogue
    split4_kernel<<<(kROWS * kHID / 4 + 255) / 256, 256>>>(px, pahi, palo, kROWS * kHID / 4);
    dim3 gQ(kMB, kHID / 128);                 // m fast, n slow
    splitT_kernel<<<dim3(kHID / 32, kHID / 32), t328>>>(pwq, pbhi, pblo, kHID, kHID);
    hgemm_fused<2><<<gQ, 256, kGemmSmem>>>(pahi, palo, pbhi, pblo, bq, pq, kROWS, kHID, kHID);
    splitT_kernel<<<dim3(kHID / 32, kHID / 32), t328>>>(pwk, pbhi, pblo, kHID, kHID);
    hgemm_fused<2><<<gQ, 256, kGemmSmem>>>(pahi, palo, pbhi, pblo, bk, pk, kROWS, kHID, kHID);
    splitT_kernel<<<dim3(kHID / 32, kHID / 32), t328>>>(pwv, pbhi, pblo, kHID, kHID);
    hgemm_fused<2><<<gQ, 256, kGemmSmem>>>(pahi, palo, pbhi, pblo, bv, pv, kROWS, kHID, kHID);

    // 4. fused flash attention (fp32 — protects floor() discontinuity)
    flash_attn_kernel<<<dim3(16, kBH), 256, kAttnSmem>>>();

    // 5. output projection + residual + LN1
    split4_kernel<<<(kROWS * kHID / 4 + 255) / 256, 256>>>(pattn, pahi, palo, kROWS * kHID / 4);
    splitT_kernel<<<dim3(kHID / 32, kHID / 32), t328>>>(Wc, pbhi, pblo, kHID, kHID);
    hgemm_fused<0><<<dim3(kMB, kHID / 128), 256, kGemmSmem>>>(pahi, palo, pbhi, pblo, bc, pff, kROWS, kHID, kHID);
    add_ln_kernel<<<kROWS, 256>>>(px, pff, ln1g, ln1b, px1);

    // 6. feed-forward + residual + LN2
    split4_kernel<<<(kROWS * kHID / 4 + 255) / 256, 256>>>(px1, pahi, palo, kROWS * kHID / 4);
    splitT_kernel<<<dim3(kFFH / 32, kHID / 32), t328>>>(W1, pbhi, pblo, kHID, kFFH);
    hgemm_fused<1><<<dim3(kMB, kFFH / 128), 256, kGemmSmem>>>(pahi, palo, pbhi, pblo, b1, ph, kROWS, kFFH, kHID);
    split4_kernel<<<(kROWS * kFFH / 4 + 255) / 256, 256>>>(ph, pahi, palo, kROWS * kFFH / 4);
    splitT_kernel<<<dim3(kHID / 32, kFFH / 32), t328>>>(W2, pbhi, pblo, kFFH, kHID);
    hgemm_fused<0><<<dim3(kMB, kHID / 128), 256, kGemmSmem>>>(pahi, palo, pbhi, pblo, b2, pff, kROWS, kHID, kFFH);
    add_ln_kernel<<<kROWS, 256>>>(px1, pff, ln2g, ln2b, px2);

    // 7. logits (dominant GEMM) on tensor cores -> d_out
    split4_kernel<<<(kROWS * kHID / 4 + 255) / 256, 256>>>(px2, pahi, palo, kROWS * kHID / 4);
    splitT_kernel<<<dim3(kVOC / 32, kHID / 32), t328>>>(Wlog, pbhi, pblo, kHID, kVOC);
    hgemm_fused<0><<<dim3(kMB, kVOC / 128), 256, kGemmSmem>>>(pahi, palo, pbhi, pblo, blog, out, kROWS, kVOC, kHID);

    (void)in_sizes; (void)n_in; (void)out_size;
}

// round 13
// speedup vs baseline: 1.4108x; 1.2908x over previous
#include <cuda_runtime.h>
#include <cuda_fp16.h>
#include <math.h>
#include <stdint.h>

// ---------------- problem constants ----------------
constexpr int kB    = 4;
constexpr int kS    = 1000;
constexpr int kHID  = 1024;
constexpr int kNH   = 16;
constexpr int kDK   = 64;
constexpr int kFFH  = 2048;
constexpr int kVOC  = 32000;
constexpr int kROWS = kB * kS;     // 4000
constexpr int kBH   = kB * kNH;    // 64

// ---------------- device scratch (no allocations allowed) ----------------
__device__ float g_pe[kHID];
__device__ float g_x   [kROWS * kHID];
__device__ float g_q   [kBH * kS * kDK];
__device__ float g_k   [kBH * kS * kDK];
__device__ float g_v   [kBH * kS * kDK];
__device__ float g_attn[kROWS * kHID];
__device__ float g_x1  [kROWS * kHID];
__device__ float g_h   [kROWS * kFFH];
__device__ float g_ff  [kROWS * kHID];
__device__ float g_x2  [kROWS * kHID];
__device__ float g_wq  [kHID * kHID];
__device__ float g_wk  [kHID * kHID];
__device__ float g_wv  [kHID * kHID];

// fp16 split pool (~98 MB): B (single fp16) | Ahi | Alo
constexpr size_t kOffBh  = 0;
constexpr size_t kOffAhi = (size_t)kHID * kVOC * 2;                 // after 65.5 MB
constexpr size_t kOffAlo = kOffAhi + (size_t)kROWS * kFFH * 2;      // +16.4 MB
constexpr size_t kPoolSz = kOffAlo + (size_t)kROWS * kFFH * 2;
__device__ __align__(256) char g_pool[kPoolSz];

// ---------------- positional encoding (source-bug constant vector) ----------------
__global__ void pe_kernel() {
    int c = threadIdx.x;                     // 0..1023
    int i = c & ~1;
    double tmp = 999.0 * exp(-(double)i / 1024.0 * log(10000.0));
    g_pe[c] = (c & 1) ? (float)cos(tmp) : (float)sin(tmp);
}

// x[row] = emb[token[row]] + pe
__global__ void embed_kernel(const int* __restrict__ tok, const float* __restrict__ emb) {
    int row = blockIdx.x;
    int t = tok[row];
    const float4* e = (const float4*)(emb + (size_t)t * kHID);
    const float4* p = (const float4*)g_pe;
    float4* xo = (float4*)(g_x + (size_t)row * kHID);
    int c = threadIdx.x;
    float4 a = e[c], b = p[c];
    xo[c] = make_float4(a.x + b.x, a.y + b.y, a.z + b.z, a.w + b.w);
}

// repack W[n][h][d] -> Wp[h][n*64+d]
__global__ void pack_w_kernel(const float* __restrict__ W, float* __restrict__ out) {
    int idx = blockIdx.x * blockDim.x + threadIdx.x;
    if (idx < kHID * kHID) {
        int h = idx >> 10;
        int col = idx & 1023;
        int n = col >> 6, d = col & 63;
        out[idx] = W[((size_t)n * kHID + h) * kDK + d];
    }
}

// ---------------- fp32 -> fp16 hi/lo split (row-major, elementwise, x4) ----------------
__global__ void split4_kernel(const float* __restrict__ in,
                              __half* __restrict__ hi,
                              __half* __restrict__ lo, int n4) {
    int i = blockIdx.x * 256 + threadIdx.x;
    if (i >= n4) return;
    float4 x = ((const float4*)in)[i];
    __half h0 = __float2half_rn(x.x), h1 = __float2half_rn(x.y);
    __half h2 = __float2half_rn(x.z), h3 = __float2half_rn(x.w);
    __half l0 = __float2half_rn(x.x - __half2float(h0));
    __half l1 = __float2half_rn(x.y - __half2float(h1));
    __half l2 = __float2half_rn(x.z - __half2float(h2));
    __half l3 = __float2half_rn(x.w - __half2float(h3));
    __half2* hp = (__half2*)hi;
    __half2* lp = (__half2*)lo;
    hp[i*2+0] = __halves2half2(h0, h1); hp[i*2+1] = __halves2half2(h2, h3);
    lp[i*2+0] = __halves2half2(l0, l1); lp[i*2+1] = __halves2half2(l2, l3);
}

// ---------------- fp32 [K,N] -> fp16 [N,K] (transpose + round, single output) ----------------
__global__ void splitT_kernel(const float* __restrict__ in,
                              __half* __restrict__ hi, int K, int N) {
    __shared__ float t[32][33];
    int n0 = blockIdx.x * 32, k0 = blockIdx.y * 32;
    int tx = threadIdx.x;
#pragma unroll
    for (int i = threadIdx.y; i < 32; i += 8)
        t[i][tx] = in[(size_t)(k0 + i) * N + n0 + tx];
    __syncthreads();
#pragma unroll
    for (int i = threadIdx.y; i < 32; i += 8)
        hi[(size_t)(n0 + i) * K + k0 + tx] = __float2half_rn(t[tx][i]);
}

// ---------------- cp.async helpers ----------------
__device__ __forceinline__ void cp16(uint32_t dst, const void* src, bool full) {
    int sz = full ? 16 : 0;
    asm volatile("cp.async.cg.shared.global [%0], [%1], 16, %2;"
                 :: "r"(dst), "l"(src), "r"(sz) : "memory");
}
__device__ __forceinline__ void cp_commit() {
    asm volatile("cp.async.commit_group;" ::: "memory");
}

// ---------------- fused fp16 2-term tensor-core GEMM ----------------
// C = (Ahi + Alo) @ B^T + bias.  A:[M,K] fp16 hi/lo pair (exact to ~2^-22),
// B:[N,K] fp16 single rounding.  Error ~ A@(B-Bf16) ~ 2^-12 relative.
// 128x128 tile, BK=32, 256 threads, 2-stage cp.async, 2 MMAs per (mi,ni).
constexpr int kPITCH = 40;
constexpr int kArrSz = 128 * kPITCH;
constexpr int kGemmSmem = 2 * 3 * kArrSz * 2;   // 61440 B

template<int EPI>
__global__ __launch_bounds__(256)
void hgemm_fused(const __half* __restrict__ aHi, const __half* __restrict__ aLo,
                 const __half* __restrict__ Bm,
                 const float* __restrict__ bias, float* __restrict__ C,
                 int M, int N, int K) {
    extern __shared__ __align__(16) __half dynsm[];
    uint32_t smbase;
    { uint64_t t64; asm("cvta.to.shared.u64 %0, %1;" : "=l"(t64) : "l"(dynsm)); smbase = (uint32_t)t64; }

    int tid = threadIdx.x;
    int wid = tid >> 5, lane = tid & 31;
    int wm = wid >> 2, wn = wid & 3;          // 2x4 warps -> warp tile 64(m) x 32(n)
    int r = lane >> 2, c2 = (lane & 3) * 2;
    int m0 = blockIdx.x * 128, n0 = blockIdx.y * 128;   // m fast

    const __half* gsrc[3] = {aHi, aLo, Bm};

    auto issue_tile = [&](int stage, int k0) {
#pragma unroll
        for (int arr = 0; arr < 3; arr++) {
            const __half* gp = gsrc[arr];
            bool isA = arr < 2;
#pragma unroll
            for (int i = 0; i < 2; i++) {
                int idx = tid + i * 256;
                int row = idx >> 2;
                int c4 = (idx & 3) * 8;
                int grow = (isA ? m0 : n0) + row;
                bool ok = isA ? (grow < M) : true;
                const void* src = gp + (size_t)(ok ? grow : 0) * K + k0 + c4;
                uint32_t dst = smbase + (uint32_t)(((stage * 3 + arr) * kArrSz + row * kPITCH + c4) * 2);
                cp16(dst, src, ok);
            }
        }
    };

    float acc[4][4][4] = {};

    issue_tile(0, 0);
    cp_commit();

    int stage = 0;
    for (int k0 = 0; k0 < K; k0 += 32) {
        bool hasNext = (k0 + 32) < K;
        if (hasNext) {
            issue_tile(stage ^ 1, k0 + 32);
            cp_commit();
            asm volatile("cp.async.wait_group 1;" ::: "memory");
        } else {
            asm volatile("cp.async.wait_group 0;" ::: "memory");
        }
        __syncthreads();

        const __half* sAhi = dynsm + (stage * 3 + 0) * kArrSz;
        const __half* sAlo = dynsm + (stage * 3 + 1) * kArrSz;
        const __half* sB   = dynsm + (stage * 3 + 2) * kArrSz;

#pragma unroll
        for (int ks = 0; ks < 32; ks += 16) {
            uint32_t ahi[4][4], alo[4][4], bfr[4][2];
#pragma unroll
            for (int mi = 0; mi < 4; mi++) {
                int rr = (wm * 64 + mi * 16 + r) * kPITCH + ks + c2;
                ahi[mi][0] = *(const uint32_t*)&sAhi[rr];
                ahi[mi][1] = *(const uint32_t*)&sAhi[rr + 8 * kPITCH];
                ahi[mi][2] = *(const uint32_t*)&sAhi[rr + 8];
                ahi[mi][3] = *(const uint32_t*)&sAhi[rr + 8 * kPITCH + 8];
                alo[mi][0] = *(const uint32_t*)&sAlo[rr];
                alo[mi][1] = *(const uint32_t*)&sAlo[rr + 8 * kPITCH];
                alo[mi][2] = *(const uint32_t*)&sAlo[rr + 8];
                alo[mi][3] = *(const uint32_t*)&sAlo[rr + 8 * kPITCH + 8];
            }
#pragma unroll
            for (int ni = 0; ni < 4; ni++) {
                int rr = (wn * 32 + ni * 8 + r) * kPITCH + ks + c2;
                bfr[ni][0] = *(const uint32_t*)&sB[rr];
                bfr[ni][1] = *(const uint32_t*)&sB[rr + 8];
            }
#define MMA(A0,A1,A2,A3,B0,B1,ACC) \
    asm volatile("mma.sync.aligned.m16n8k16.row.col.f32.f16.f16.f32 " \
                 "{%0,%1,%2,%3}, {%4,%5,%6,%7}, {%8,%9}, {%0,%1,%2,%3};" \
                 : "+f"(ACC[0]), "+f"(ACC[1]), "+f"(ACC[2]), "+f"(ACC[3]) \
                 : "r"(A0), "r"(A1), "r"(A2), "r"(A3), "r"(B0), "r"(B1))
#pragma unroll
            for (int mi = 0; mi < 4; mi++)
#pragma unroll
                for (int ni = 0; ni < 4; ni++) {
                    MMA(ahi[mi][0], ahi[mi][1], ahi[mi][2], ahi[mi][3],
                        bfr[ni][0], bfr[ni][1], acc[mi][ni]);
                    MMA(alo[mi][0], alo[mi][1], alo[mi][2], alo[mi][3],
                        bfr[ni][0], bfr[ni][1], acc[mi][ni]);
                }
#undef MMA
        }
        __syncthreads();
        stage ^= 1;
    }

#pragma unroll
    for (int mi = 0; mi < 4; mi++) {
#pragma unroll
        for (int half = 0; half < 2; half++) {
            int row = m0 + wm * 64 + mi * 16 + r + half * 8;
            if (row >= M) continue;
#pragma unroll
            for (int ni = 0; ni < 4; ni++) {
                int col = n0 + wn * 32 + ni * 8 + c2;
                float v0 = acc[mi][ni][half * 2 + 0] + bias[col];
                float v1 = acc[mi][ni][half * 2 + 1] + bias[col + 1];
                if (EPI == 1) { v0 = fmaxf(v0, 0.f); v1 = fmaxf(v1, 0.f); }
                if (EPI == 2) {
                    int b = row / kS, s = row % kS;
                    int n = col >> 6, d = col & 63;
                    size_t base = (((size_t)(b * kNH + n)) * kS + s) * kDK + d;
                    C[base] = v0; C[base + 1] = v1;
                } else {
                    *(float2*)&C[(size_t)row * N + col] = make_float2(v0, v1);
                }
            }
        }
    }
}

// ---------------- fused flash attention ----------------
constexpr int kAttnSmem = 4 * 64 * 68 * 4;

__global__ __launch_bounds__(256)
void flash_attn_kernel() {
    extern __shared__ float asm_[];
    float (*Ks)[68] = (float(*)[68])asm_;
    float (*Qs)[68] = (float(*)[68])(asm_ + 64 * 68);
    float (*Vs)[68] = (float(*)[68])(asm_ + 2 * 64 * 68);
    float (*Ps)[68] = (float(*)[68])(asm_ + 3 * 64 * 68);

    int bh = blockIdx.y;
    int s0 = blockIdx.x * 64;
    const float* kp = g_k + (size_t)bh * kS * kDK;
    const float* qp = g_q + (size_t)bh * kS * kDK;
    const float* vp = g_v + (size_t)bh * kS * kDK;
    int tid = threadIdx.x;
    int tr = tid >> 4, tc = tid & 15;

#pragma unroll
    for (int i = 0; i < 4; i++) {
        int idx = tid + i * 256;
        int r = idx >> 4;
        int c = (idx & 15) << 2;
        float4 vk = (s0 + r < kS) ? *(const float4*)&kp[(size_t)(s0 + r) * kDK + c]
                                  : make_float4(0.f, 0.f, 0.f, 0.f);
        Ks[c + 0][r] = vk.x; Ks[c + 1][r] = vk.y; Ks[c + 2][r] = vk.z; Ks[c + 3][r] = vk.w;
    }

    float m_run[4], l_run[4], acc[4][4];
#pragma unroll
    for (int i = 0; i < 4; i++) {
        m_run[i] = -1e30f; l_run[i] = 0.f;
#pragma unroll
        for (int j = 0; j < 4; j++) acc[i][j] = 0.f;
    }

    for (int t0 = 0; t0 <= s0; t0 += 64) {
        __syncthreads();
#pragma unroll
        for (int i = 0; i < 4; i++) {
            int idx = tid + i * 256;
            int r = idx >> 4;
            int c = (idx & 15) << 2;
            bool ok = (t0 + r < kS);
            float4 vq = ok ? *(const float4*)&qp[(size_t)(t0 + r) * kDK + c]
                           : make_float4(0.f, 0.f, 0.f, 0.f);
            Qs[c + 0][r] = vq.x; Qs[c + 1][r] = vq.y; Qs[c + 2][r] = vq.z; Qs[c + 3][r] = vq.w;
            float4 vv = ok ? *(const float4*)&vp[(size_t)(t0 + r) * kDK + c]
                           : make_float4(0.f, 0.f, 0.f, 0.f);
            *(float4*)&Vs[r][c] = vv;
        }
        __syncthreads();

        float S[4][4] = {};
#pragma unroll
        for (int d = 0; d < 64; d++) {
            float ra[4], rb[4];
#pragma unroll
            for (int i = 0; i < 4; i++) ra[i] = Ks[d][tr * 4 + i];
#pragma unroll
            for (int j = 0; j < 4; j++) rb[j] = Qs[d][tc * 4 + j];
#pragma unroll
            for (int i = 0; i < 4; i++)
#pragma unroll
                for (int j = 0; j < 4; j++) S[i][j] += ra[i] * rb[j];
        }
#pragma unroll
        for (int i = 0; i < 4; i++) {
            int s = s0 + tr * 4 + i;
#pragma unroll
            for (int j = 0; j < 4; j++) {
                int t = t0 + tc * 4 + j;
                S[i][j] = (t > s) ? -INFINITY : floorf(S[i][j] * 0.125f);
            }
        }
        float corr[4];
#pragma unroll
        for (int i = 0; i < 4; i++) {
            float mt = fmaxf(fmaxf(S[i][0], S[i][1]), fmaxf(S[i][2], S[i][3]));
#pragma unroll
            for (int o = 8; o; o >>= 1) mt = fmaxf(mt, __shfl_xor_sync(0xffffffffu, mt, o, 16));
            float nm = fmaxf(m_run[i], mt);
            corr[i] = expf(m_run[i] - nm);
            m_run[i] = nm;
            float ls = 0.f;
#pragma unroll
            for (int j = 0; j < 4; j++) {
                float p = expf(S[i][j] - nm);
                S[i][j] = p;
                ls += p;
            }
#pragma unroll
            for (int o = 8; o; o >>= 1) ls += __shfl_xor_sync(0xffffffffu, ls, o, 16);
            l_run[i] = l_run[i] * corr[i] + ls;
#pragma unroll
            for (int j = 0; j < 4; j++) acc[i][j] *= corr[i];
        }
#pragma unroll
        for (int i = 0; i < 4; i++)
#pragma unroll
            for (int j = 0; j < 4; j++)
                Ps[tc * 4 + j][tr * 4 + i] = S[i][j];
        __syncthreads();

#pragma unroll
        for (int k = 0; k < 64; k++) {
            float ra[4], rb[4];
#pragma unroll
            for (int i = 0; i < 4; i++) ra[i] = Ps[k][tr * 4 + i];
#pragma unroll
            for (int j = 0; j < 4; j++) rb[j] = Vs[k][tc * 4 + j];
#pragma unroll
            for (int i = 0; i < 4; i++)
#pragma unroll
                for (int j = 0; j < 4; j++) acc[i][j] += ra[i] * rb[j];
        }
    }

    int b = bh >> 4, n = bh & 15;
#pragma unroll
    for (int i = 0; i < 4; i++) {
        int s = s0 + tr * 4 + i;
        if (s >= kS) continue;
        float inv = 1.f / l_run[i];
#pragma unroll
        for (int j = 0; j < 4; j++) {
            g_attn[((size_t)(b * kS + s)) * kHID + n * kDK + tc * 4 + j] = acc[i][j] * inv;
        }
    }
}

// ---------------- out = LayerNorm(x + delta) * g + b ----------------
__global__ __launch_bounds__(256)
void add_ln_kernel(const float* __restrict__ xin, const float* __restrict__ dl,
                   const float* __restrict__ g, const float* __restrict__ b,
                   float* __restrict__ out) {
    int row = blockIdx.x;
    int tid = threadIdx.x;
    const float* xr = xin + (size_t)row * kHID;
    const float* dr = dl  + (size_t)row * kHID;
    __shared__ float red[256];

    float v[4]; float ls = 0.f;
#pragma unroll
    for (int i = 0; i < 4; i++) { int c = tid + i * 256; v[i] = xr[c] + dr[c]; ls += v[i]; }
    red[tid] = ls; __syncthreads();
    for (int o = 128; o; o >>= 1) { if (tid < o) red[tid] += red[tid + o]; __syncthreads(); }
    float mu = red[0] * (1.f / kHID);
    __syncthreads();

    float lv = 0.f;
#pragma unroll
    for (int i = 0; i < 4; i++) { float d = v[i] - mu; lv += d * d; }
    red[tid] = lv; __syncthreads();
    for (int o = 128; o; o >>= 1) { if (tid < o) red[tid] += red[tid + o]; __syncthreads(); }
    float rstd = 1.f / sqrtf(red[0] * (1.f / kHID) + 1e-5f);

    float* orow = out + (size_t)row * kHID;
#pragma unroll
    for (int i = 0; i < 4; i++) {
        int c = tid + i * 256;
        orow[c] = (v[i] - mu) * rstd * g[c] + b[c];
    }
}

// ---------------- launcher ----------------
extern "C" void kernel_launch(void* const* d_in, const int* in_sizes, int n_in,
                              void* d_out, int out_size) {
    const int*   tok  = (const int*)  d_in[0];
    const float* emb  = (const float*)d_in[1];
    const float* Wq   = (const float*)d_in[2];
    const float* bq   = (const float*)d_in[3];
    const float* Wk   = (const float*)d_in[4];
    const float* bk   = (const float*)d_in[5];
    const float* Wv   = (const float*)d_in[6];
    const float* bv   = (const float*)d_in[7];
    const float* Wc   = (const float*)d_in[8];
    const float* bc   = (const float*)d_in[9];
    const float* ln1g = (const float*)d_in[10];
    const float* ln1b = (const float*)d_in[11];
    const float* W1   = (const float*)d_in[12];
    const float* b1   = (const float*)d_in[13];
    const float* W2   = (const float*)d_in[14];
    const float* b2   = (const float*)d_in[15];
    const float* ln2g = (const float*)d_in[16];
    const float* ln2b = (const float*)d_in[17];
    const float* Wlog = (const float*)d_in[18];
    const float* blog = (const float*)d_in[19];
    float* out = (float*)d_out;

    float *px, *pq, *pk, *pv, *pattn, *px1, *ph, *pff, *px2, *pwq, *pwk, *pwv;
    char* ppool;
    cudaGetSymbolAddress((void**)&px,    g_x);
    cudaGetSymbolAddress((void**)&pq,    g_q);
    cudaGetSymbolAddress((void**)&pk,    g_k);
    cudaGetSymbolAddress((void**)&pv,    g_v);
    cudaGetSymbolAddress((void**)&pattn, g_attn);
    cudaGetSymbolAddress((void**)&px1,   g_x1);
    cudaGetSymbolAddress((void**)&ph,    g_h);
    cudaGetSymbolAddress((void**)&pff,   g_ff);
    cudaGetSymbolAddress((void**)&px2,   g_x2);
    cudaGetSymbolAddress((void**)&pwq,   g_wq);
    cudaGetSymbolAddress((void**)&pwk,   g_wk);
    cudaGetSymbolAddress((void**)&pwv,   g_wv);
    cudaGetSymbolAddress((void**)&ppool, g_pool);

    __half* pbh  = (__half*)(ppool + kOffBh);
    __half* pahi = (__half*)(ppool + kOffAhi);
    __half* palo = (__half*)(ppool + kOffAlo);

    cudaFuncSetAttribute(hgemm_fused<0>, cudaFuncAttributeMaxDynamicSharedMemorySize, kGemmSmem);
    cudaFuncSetAttribute(hgemm_fused<1>, cudaFuncAttributeMaxDynamicSharedMemorySize, kGemmSmem);
    cudaFuncSetAttribute(hgemm_fused<2>, cudaFuncAttributeMaxDynamicSharedMemorySize, kGemmSmem);
    cudaFuncSetAttribute(flash_attn_kernel, cudaFuncAttributeMaxDynamicSharedMemorySize, kAttnSmem);

    dim3 t328(32, 8);
    constexpr int kMB = (kROWS + 127) / 128;   // 32 m-blocks

    // 1. positional encoding + embedding
    pe_kernel<<<1, 1024>>>();
    embed_kernel<<<kROWS, 256>>>(tok, emb);

    // 2. repack per-head QKV weights into [HID, HID] fp32
    pack_w_kernel<<<(kHID * kHID + 255) / 256, 256>>>(Wq, pwq);
    pack_w_kernel<<<(kHID * kHID + 255) / 256, 256>>>(Wk, pwk);
    pack_w_kernel<<<(kHID * kHID + 255) / 256, 256>>>(Wv, pwv);

    // 3. QKV projections on tensor cores (fp16 2-term), scatter epilogue
    split4_kernel<<<(kROWS * kHID / 4 + 255) / 256, 256>>>(px, pahi, palo, kROWS * kHID / 4);
    dim3 gQ(kMB, kHID / 128);
    splitT_kernel<<<dim3(kHID / 32, kHID / 32), t328>>>(pwq, pbh, kHID, kHID);
    hgemm_fused<2><<<gQ, 256, kGemmSmem>>>(pahi, palo, pbh, bq, pq, kROWS, kHID, kHID);
    splitT_kernel<<<dim3(kHID / 32, kHID / 32), t328>>>(pwk, pbh, kHID, kHID);
    hgemm_fused<2><<<gQ, 256, kGemmSmem>>>(pahi, palo, pbh, bk, pk, kROWS, kHID, kHID);
    splitT_kernel<<<dim3(kHID / 32, kHID / 32), t328>>>(pwv, pbh, kHID, kHID);
    hgemm_fused<2><<<gQ, 256, kGemmSmem>>>(pahi, palo, pbh, bv, pv, kROWS, kHID, kHID);

    // 4. fused flash attention (fp32 — protects floor() discontinuity)
    flash_attn_kernel<<<dim3(16, kBH), 256, kAttnSmem>>>();

    // 5. output projection + residual + LN1
    split4_kernel<<<(kROWS * kHID / 4 + 255) / 256, 256>>>(pattn, pahi, palo, kROWS * kHID / 4);
    splitT_kernel<<<dim3(kHID / 32, kHID / 32), t328>>>(Wc, pbh, kHID, kHID);
    hgemm_fused<0><<<dim3(kMB, kHID / 128), 256, kGemmSmem>>>(pahi, palo, pbh, bc, pff, kROWS, kHID, kHID);
    add_ln_kernel<<<kROWS, 256>>>(px, pff, ln1g, ln1b, px1);

    // 6. feed-forward + residual + LN2
    split4_kernel<<<(kROWS * kHID / 4 + 255) / 256, 256>>>(px1, pahi, palo, kROWS * kHID / 4);
    splitT_kernel<<<dim3(kFFH / 32, kHID / 32), t328>>>(W1, pbh, kHID, kFFH);
    hgemm_fused<1><<<dim3(kMB, kFFH / 128), 256, kGemmSmem>>>(pahi, palo, pbh, b1, ph, kROWS, kFFH, kHID);
    split4_kernel<<<(kROWS * kFFH / 4 + 255) / 256, 256>>>(ph, pahi, palo, kROWS * kFFH / 4);
    splitT_kernel<<<dim3(kHID / 32, kFFH / 32), t328>>>(W2, pbh, kFFH, kHID);
    hgemm_fused<0><<<dim3(kMB, kHID / 128), 256, kGemmSmem>>>(pahi, palo, pbh, b2, pff, kROWS, kHID, kFFH);
    add_ln_kernel<<<kROWS, 256>>>(px1, pff, ln2g, ln2b, px2);

    // 7. logits (dominant GEMM) on tensor cores -> d_out
    split4_kernel<<<(kROWS * kHID / 4 + 255) / 256, 256>>>(px2, pahi, palo, kROWS * kHID / 4);
    splitT_kernel<<<dim3(kVOC / 32, kHID / 32), t328>>>(Wlog, pbh, kHID, kVOC);
    hgemm_fused<0><<<dim3(kMB, kVOC / 128), 256, kGemmSmem>>>(pahi, palo, pbh, blog, out, kROWS, kVOC, kHID);

    (void)in_sizes; (void)n_in; (void)out_size;
}

// round 15
// speedup vs baseline: 1.8285x; 1.2961x over previous
#include <cuda_runtime.h>
#include <cuda_fp16.h>
#include <math.h>
#include <stdint.h>

// ---------------- problem constants ----------------
constexpr int kB    = 4;
constexpr int kS    = 1000;
constexpr int kHID  = 1024;
constexpr int kNH   = 16;
constexpr int kDK   = 64;
constexpr int kFFH  = 2048;
constexpr int kVOC  = 32000;
constexpr int kROWS = kB * kS;     // 4000
constexpr int kBH   = kB * kNH;    // 64

// ---------------- device scratch (no allocations allowed) ----------------
__device__ float g_pe[kHID];
__device__ float g_x   [kROWS * kHID];
__device__ float g_q   [kBH * kS * kDK];
__device__ float g_k   [kBH * kS * kDK];
__device__ float g_v   [kBH * kS * kDK];
__device__ float g_attn[kROWS * kHID];
__device__ float g_x1  [kROWS * kHID];
__device__ float g_h   [kROWS * kFFH];
__device__ float g_ff  [kROWS * kHID];
__device__ float g_x2  [kROWS * kHID];
__device__ float g_wq  [kHID * kHID];
__device__ float g_wk  [kHID * kHID];
__device__ float g_wv  [kHID * kHID];

// fp16 split pool (~98 MB): B (single fp16) | Ahi | Alo
constexpr size_t kOffBh  = 0;
constexpr size_t kOffAhi = (size_t)kHID * kVOC * 2;                 // after 65.5 MB
constexpr size_t kOffAlo = kOffAhi + (size_t)kROWS * kFFH * 2;      // +16.4 MB
constexpr size_t kPoolSz = kOffAlo + (size_t)kROWS * kFFH * 2;
__device__ __align__(256) char g_pool[kPoolSz];

// ---------------- positional encoding (source-bug constant vector) ----------------
__global__ void pe_kernel() {
    int c = threadIdx.x;                     // 0..1023
    int i = c & ~1;
    double tmp = 999.0 * exp(-(double)i / 1024.0 * log(10000.0));
    g_pe[c] = (c & 1) ? (float)cos(tmp) : (float)sin(tmp);
}

// x[row] = emb[token[row]] + pe
__global__ void embed_kernel(const int* __restrict__ tok, const float* __restrict__ emb) {
    int row = blockIdx.x;
    int t = tok[row];
    const float4* e = (const float4*)(emb + (size_t)t * kHID);
    const float4* p = (const float4*)g_pe;
    float4* xo = (float4*)(g_x + (size_t)row * kHID);
    int c = threadIdx.x;
    float4 a = e[c], b = p[c];
    xo[c] = make_float4(a.x + b.x, a.y + b.y, a.z + b.z, a.w + b.w);
}

// repack W[n][h][d] -> Wp[h][n*64+d]
__global__ void pack_w_kernel(const float* __restrict__ W, float* __restrict__ out) {
    int idx = blockIdx.x * blockDim.x + threadIdx.x;
    if (idx < kHID * kHID) {
        int h = idx >> 10;
        int col = idx & 1023;
        int n = col >> 6, d = col & 63;
        out[idx] = W[((size_t)n * kHID + h) * kDK + d];
    }
}

// ---------------- fp32 -> fp16 hi/lo split (row-major, elementwise, x4) ----------------
__global__ void split4_kernel(const float* __restrict__ in,
                              __half* __restrict__ hi,
                              __half* __restrict__ lo, int n4) {
    int i = blockIdx.x * 256 + threadIdx.x;
    if (i >= n4) return;
    float4 x = ((const float4*)in)[i];
    __half h0 = __float2half_rn(x.x), h1 = __float2half_rn(x.y);
    __half h2 = __float2half_rn(x.z), h3 = __float2half_rn(x.w);
    __half l0 = __float2half_rn(x.x - __half2float(h0));
    __half l1 = __float2half_rn(x.y - __half2float(h1));
    __half l2 = __float2half_rn(x.z - __half2float(h2));
    __half l3 = __float2half_rn(x.w - __half2float(h3));
    __half2* hp = (__half2*)hi;
    __half2* lp = (__half2*)lo;
    hp[i*2+0] = __halves2half2(h0, h1); hp[i*2+1] = __halves2half2(h2, h3);
    lp[i*2+0] = __halves2half2(l0, l1); lp[i*2+1] = __halves2half2(l2, l3);
}

// ---------------- fp32 [K,N] -> fp16 [N,K] (transpose + round, single output) ----------------
__global__ void splitT_kernel(const float* __restrict__ in,
                              __half* __restrict__ hi, int K, int N) {
    __shared__ float t[32][33];
    int n0 = blockIdx.x * 32, k0 = blockIdx.y * 32;
    int tx = threadIdx.x;
#pragma unroll
    for (int i = threadIdx.y; i < 32; i += 8)
        t[i][tx] = in[(size_t)(k0 + i) * N + n0 + tx];
    __syncthreads();
#pragma unroll
    for (int i = threadIdx.y; i < 32; i += 8)
        hi[(size_t)(n0 + i) * K + k0 + tx] = __float2half_rn(t[tx][i]);
}

// ---------------- cp.async helpers ----------------
__device__ __forceinline__ void cp16(uint32_t dst, const void* src, bool full) {
    int sz = full ? 16 : 0;
    asm volatile("cp.async.cg.shared.global [%0], [%1], 16, %2;"
                 :: "r"(dst), "l"(src), "r"(sz) : "memory");
}
__device__ __forceinline__ void cp_commit() {
    asm volatile("cp.async.commit_group;" ::: "memory");
}

// ---------------- fused fp16 tensor-core GEMM ----------------
// TERMS=2: C = (Ahi + Alo) @ B^T + bias (A exact to ~2^-22, err ~ A@(B-Bh) ~ 2e-4)
// TERMS=1: C = Ahi @ B^T + bias          (adds (A-Ah)@Bh ~ 2e-4 more; logits only)
// 128x128 tile, BK=32, 256 threads, 2-stage cp.async.
constexpr int kPITCH = 40;
constexpr int kArrSz = 128 * kPITCH;
constexpr int kGemmSmem = 2 * 3 * kArrSz * 2;   // 61440 B (TERMS=1 uses 2/3 of it)

template<int EPI, int TERMS>
__global__ __launch_bounds__(256)
void hgemm_fused(const __half* __restrict__ aHi, const __half* __restrict__ aLo,
                 const __half* __restrict__ Bm,
                 const float* __restrict__ bias, float* __restrict__ C,
                 int M, int N, int K) {
    extern __shared__ __align__(16) __half dynsm[];
    uint32_t smbase;
    { uint64_t t64; asm("cvta.to.shared.u64 %0, %1;" : "=l"(t64) : "l"(dynsm)); smbase = (uint32_t)t64; }

    int tid = threadIdx.x;
    int wid = tid >> 5, lane = tid & 31;
    int wm = wid >> 2, wn = wid & 3;          // 2x4 warps -> warp tile 64(m) x 32(n)
    int r = lane >> 2, c2 = (lane & 3) * 2;
    int m0 = blockIdx.x * 128, n0 = blockIdx.y * 128;   // m fast

    const __half* gsrc[3] = {aHi, aLo, Bm};

    auto issue_tile = [&](int stage, int k0) {
#pragma unroll
        for (int arr = 0; arr < 3; arr++) {
            if (TERMS == 1 && arr == 1) continue;      // skip Alo traffic entirely
            const __half* gp = gsrc[arr];
            bool isA = arr < 2;
#pragma unroll
            for (int i = 0; i < 2; i++) {
                int idx = tid + i * 256;
                int row = idx >> 2;
                int c4 = (idx & 3) * 8;
                int grow = (isA ? m0 : n0) + row;
                bool ok = isA ? (grow < M) : true;
                const void* src = gp + (size_t)(ok ? grow : 0) * K + k0 + c4;
                uint32_t dst = smbase + (uint32_t)(((stage * 3 + arr) * kArrSz + row * kPITCH + c4) * 2);
                cp16(dst, src, ok);
            }
        }
    };

    float acc[4][4][4] = {};

    issue_tile(0, 0);
    cp_commit();

    int stage = 0;
    for (int k0 = 0; k0 < K; k0 += 32) {
        bool hasNext = (k0 + 32) < K;
        if (hasNext) {
            issue_tile(stage ^ 1, k0 + 32);
            cp_commit();
            asm volatile("cp.async.wait_group 1;" ::: "memory");
        } else {
            asm volatile("cp.async.wait_group 0;" ::: "memory");
        }
        __syncthreads();

        const __half* sAhi = dynsm + (stage * 3 + 0) * kArrSz;
        const __half* sAlo = dynsm + (stage * 3 + 1) * kArrSz;
        const __half* sB   = dynsm + (stage * 3 + 2) * kArrSz;

#pragma unroll
        for (int ks = 0; ks < 32; ks += 16) {
            uint32_t ahi[4][4], alo[4][4], bfr[4][2];
#pragma unroll
            for (int mi = 0; mi < 4; mi++) {
                int rr = (wm * 64 + mi * 16 + r) * kPITCH + ks + c2;
                ahi[mi][0] = *(const uint32_t*)&sAhi[rr];
                ahi[mi][1] = *(const uint32_t*)&sAhi[rr + 8 * kPITCH];
                ahi[mi][2] = *(const uint32_t*)&sAhi[rr + 8];
                ahi[mi][3] = *(const uint32_t*)&sAhi[rr + 8 * kPITCH + 8];
                if (TERMS == 2) {
                    alo[mi][0] = *(const uint32_t*)&sAlo[rr];
                    alo[mi][1] = *(const uint32_t*)&sAlo[rr + 8 * kPITCH];
                    alo[mi][2] = *(const uint32_t*)&sAlo[rr + 8];
                    alo[mi][3] = *(const uint32_t*)&sAlo[rr + 8 * kPITCH + 8];
                }
            }
#pragma unroll
            for (int ni = 0; ni < 4; ni++) {
                int rr = (wn * 32 + ni * 8 + r) * kPITCH + ks + c2;
                bfr[ni][0] = *(const uint32_t*)&sB[rr];
                bfr[ni][1] = *(const uint32_t*)&sB[rr + 8];
            }
#define MMA(A0,A1,A2,A3,B0,B1,ACC) \
    asm volatile("mma.sync.aligned.m16n8k16.row.col.f32.f16.f16.f32 " \
                 "{%0,%1,%2,%3}, {%4,%5,%6,%7}, {%8,%9}, {%0,%1,%2,%3};" \
                 : "+f"(ACC[0]), "+f"(ACC[1]), "+f"(ACC[2]), "+f"(ACC[3]) \
                 : "r"(A0), "r"(A1), "r"(A2), "r"(A3), "r"(B0), "r"(B1))
#pragma unroll
            for (int mi = 0; mi < 4; mi++)
#pragma unroll
                for (int ni = 0; ni < 4; ni++) {
                    MMA(ahi[mi][0], ahi[mi][1], ahi[mi][2], ahi[mi][3],
                        bfr[ni][0], bfr[ni][1], acc[mi][ni]);
                    if (TERMS == 2)
                        MMA(alo[mi][0], alo[mi][1], alo[mi][2], alo[mi][3],
                            bfr[ni][0], bfr[ni][1], acc[mi][ni]);
                }
#undef MMA
        }
        __syncthreads();
        stage ^= 1;
    }

#pragma unroll
    for (int mi = 0; mi < 4; mi++) {
#pragma unroll
        for (int half = 0; half < 2; half++) {
            int row = m0 + wm * 64 + mi * 16 + r + half * 8;
            if (row >= M) continue;
#pragma unroll
            for (int ni = 0; ni < 4; ni++) {
                int col = n0 + wn * 32 + ni * 8 + c2;
                float v0 = acc[mi][ni][half * 2 + 0] + bias[col];
                float v1 = acc[mi][ni][half * 2 + 1] + bias[col + 1];
                if (EPI == 1) { v0 = fmaxf(v0, 0.f); v1 = fmaxf(v1, 0.f); }
                if (EPI == 2) {
                    int b = row / kS, s = row % kS;
                    int n = col >> 6, d = col & 63;
                    size_t base = (((size_t)(b * kNH + n)) * kS + s) * kDK + d;
                    C[base] = v0; C[base + 1] = v1;
                } else {
                    *(float2*)&C[(size_t)row * N + col] = make_float2(v0, v1);
                }
            }
        }
    }
}

// ---------------- fused flash attention ----------------
constexpr int kAttnSmem = 4 * 64 * 68 * 4;

__global__ __launch_bounds__(256)
void flash_attn_kernel() {
    extern __shared__ float asm_[];
    float (*Ks)[68] = (float(*)[68])asm_;
    float (*Qs)[68] = (float(*)[68])(asm_ + 64 * 68);
    float (*Vs)[68] = (float(*)[68])(asm_ + 2 * 64 * 68);
    float (*Ps)[68] = (float(*)[68])(asm_ + 3 * 64 * 68);

    int bh = blockIdx.y;
    int s0 = blockIdx.x * 64;
    const float* kp = g_k + (size_t)bh * kS * kDK;
    const float* qp = g_q + (size_t)bh * kS * kDK;
    const float* vp = g_v + (size_t)bh * kS * kDK;
    int tid = threadIdx.x;
    int tr = tid >> 4, tc = tid & 15;

#pragma unroll
    for (int i = 0; i < 4; i++) {
        int idx = tid + i * 256;
        int r = idx >> 4;
        int c = (idx & 15) << 2;
        float4 vk = (s0 + r < kS) ? *(const float4*)&kp[(size_t)(s0 + r) * kDK + c]
                                  : make_float4(0.f, 0.f, 0.f, 0.f);
        Ks[c + 0][r] = vk.x; Ks[c + 1][r] = vk.y; Ks[c + 2][r] = vk.z; Ks[c + 3][r] = vk.w;
    }

    float m_run[4], l_run[4], acc[4][4];
#pragma unroll
    for (int i = 0; i < 4; i++) {
        m_run[i] = -1e30f; l_run[i] = 0.f;
#pragma unroll
        for (int j = 0; j < 4; j++) acc[i][j] = 0.f;
    }

    for (int t0 = 0; t0 <= s0; t0 += 64) {
        __syncthreads();
#pragma unroll
        for (int i = 0; i < 4; i++) {
            int idx = tid + i * 256;
            int r = idx >> 4;
            int c = (idx & 15) << 2;
            bool ok = (t0 + r < kS);
            float4 vq = ok ? *(const float4*)&qp[(size_t)(t0 + r) * kDK + c]
                           : make_float4(0.f, 0.f, 0.f, 0.f);
            Qs[c + 0][r] = vq.x; Qs[c + 1][r] = vq.y; Qs[c + 2][r] = vq.z; Qs[c + 3][r] = vq.w;
            float4 vv = ok ? *(const float4*)&vp[(size_t)(t0 + r) * kDK + c]
                           : make_float4(0.f, 0.f, 0.f, 0.f);
            *(float4*)&Vs[r][c] = vv;
        }
        __syncthreads();

        float S[4][4] = {};
#pragma unroll
        for (int d = 0; d < 64; d++) {
            float ra[4], rb[4];
#pragma unroll
            for (int i = 0; i < 4; i++) ra[i] = Ks[d][tr * 4 + i];
#pragma unroll
            for (int j = 0; j < 4; j++) rb[j] = Qs[d][tc * 4 + j];
#pragma unroll
            for (int i = 0; i < 4; i++)
#pragma unroll
                for (int j = 0; j < 4; j++) S[i][j] += ra[i] * rb[j];
        }
#pragma unroll
        for (int i = 0; i < 4; i++) {
            int s = s0 + tr * 4 + i;
#pragma unroll
            for (int j = 0; j < 4; j++) {
                int t = t0 + tc * 4 + j;
                S[i][j] = (t > s) ? -INFINITY : floorf(S[i][j] * 0.125f);
            }
        }
        float corr[4];
#pragma unroll
        for (int i = 0; i < 4; i++) {
            float mt = fmaxf(fmaxf(S[i][0], S[i][1]), fmaxf(S[i][2], S[i][3]));
#pragma unroll
            for (int o = 8; o; o >>= 1) mt = fmaxf(mt, __shfl_xor_sync(0xffffffffu, mt, o, 16));
            float nm = fmaxf(m_run[i], mt);
            corr[i] = expf(m_run[i] - nm);
            m_run[i] = nm;
            float ls = 0.f;
#pragma unroll
            for (int j = 0; j < 4; j++) {
                float p = expf(S[i][j] - nm);
                S[i][j] = p;
                ls += p;
            }
#pragma unroll
            for (int o = 8; o; o >>= 1) ls += __shfl_xor_sync(0xffffffffu, ls, o, 16);
            l_run[i] = l_run[i] * corr[i] + ls;
#pragma unroll
            for (int j = 0; j < 4; j++) acc[i][j] *= corr[i];
        }
#pragma unroll
        for (int i = 0; i < 4; i++)
#pragma unroll
            for (int j = 0; j < 4; j++)
                Ps[tc * 4 + j][tr * 4 + i] = S[i][j];
        __syncthreads();

#pragma unroll
        for (int k = 0; k < 64; k++) {
            float ra[4], rb[4];
#pragma unroll
            for (int i = 0; i < 4; i++) ra[i] = Ps[k][tr * 4 + i];
#pragma unroll
            for (int j = 0; j < 4; j++) rb[j] = Vs[k][tc * 4 + j];
#pragma unroll
            for (int i = 0; i < 4; i++)
#pragma unroll
                for (int j = 0; j < 4; j++) acc[i][j] += ra[i] * rb[j];
        }
    }

    int b = bh >> 4, n = bh & 15;
#pragma unroll
    for (int i = 0; i < 4; i++) {
        int s = s0 + tr * 4 + i;
        if (s >= kS) continue;
        float inv = 1.f / l_run[i];
#pragma unroll
        for (int j = 0; j < 4; j++) {
            g_attn[((size_t)(b * kS + s)) * kHID + n * kDK + tc * 4 + j] = acc[i][j] * inv;
        }
    }
}

// ---------------- out = LayerNorm(x + delta) * g + b ----------------
__global__ __launch_bounds__(256)
void add_ln_kernel(const float* __restrict__ xin, const float* __restrict__ dl,
                   const float* __restrict__ g, const float* __restrict__ b,
                   float* __restrict__ out) {
    int row = blockIdx.x;
    int tid = threadIdx.x;
    const float* xr = xin + (size_t)row * kHID;
    const float* dr = dl  + (size_t)row * kHID;
    __shared__ float red[256];

    float v[4]; float ls = 0.f;
#pragma unroll
    for (int i = 0; i < 4; i++) { int c = tid + i * 256; v[i] = xr[c] + dr[c]; ls += v[i]; }
    red[tid] = ls; __syncthreads();
    for (int o = 128; o; o >>= 1) { if (tid < o) red[tid] += red[tid + o]; __syncthreads(); }
    float mu = red[0] * (1.f / kHID);
    __syncthreads();

    float lv = 0.f;
#pragma unroll
    for (int i = 0; i < 4; i++) { float d = v[i] - mu; lv += d * d; }
    red[tid] = lv; __syncthreads();
    for (int o = 128; o; o >>= 1) { if (tid < o) red[tid] += red[tid + o]; __syncthreads(); }
    float rstd = 1.f / sqrtf(red[0] * (1.f / kHID) + 1e-5f);

    float* orow = out + (size_t)row * kHID;
#pragma unroll
    for (int i = 0; i < 4; i++) {
        int c = tid + i * 256;
        orow[c] = (v[i] - mu) * rstd * g[c] + b[c];
    }
}

// ---------------- launcher ----------------
extern "C" void kernel_launch(void* const* d_in, const int* in_sizes, int n_in,
                              void* d_out, int out_size) {
    const int*   tok  = (const int*)  d_in[0];
    const float* emb  = (const float*)d_in[1];
    const float* Wq   = (const float*)d_in[2];
    const float* bq   = (const float*)d_in[3];
    const float* Wk   = (const float*)d_in[4];
    const float* bk   = (const float*)d_in[5];
    const float* Wv   = (const float*)d_in[6];
    const float* bv   = (const float*)d_in[7];
    const float* Wc   = (const float*)d_in[8];
    const float* bc   = (const float*)d_in[9];
    const float* ln1g = (const float*)d_in[10];
    const float* ln1b = (const float*)d_in[11];
    const float* W1   = (const float*)d_in[12];
    const float* b1   = (const float*)d_in[13];
    const float* W2   = (const float*)d_in[14];
    const float* b2   = (const float*)d_in[15];
    const float* ln2g = (const float*)d_in[16];
    const float* ln2b = (const float*)d_in[17];
    const float* Wlog = (const float*)d_in[18];
    const float* blog = (const float*)d_in[19];
    float* out = (float*)d_out;

    float *px, *pq, *pk, *pv, *pattn, *px1, *ph, *pff, *px2, *pwq, *pwk, *pwv;
    char* ppool;
    cudaGetSymbolAddress((void**)&px,    g_x);
    cudaGetSymbolAddress((void**)&pq,    g_q);
    cudaGetSymbolAddress((void**)&pk,    g_k);
    cudaGetSymbolAddress((void**)&pv,    g_v);
    cudaGetSymbolAddress((void**)&pattn, g_attn);
    cudaGetSymbolAddress((void**)&px1,   g_x1);
    cudaGetSymbolAddress((void**)&ph,    g_h);
    cudaGetSymbolAddress((void**)&pff,   g_ff);
    cudaGetSymbolAddress((void**)&px2,   g_x2);
    cudaGetSymbolAddress((void**)&pwq,   g_wq);
    cudaGetSymbolAddress((void**)&pwk,   g_wk);
    cudaGetSymbolAddress((void**)&pwv,   g_wv);
    cudaGetSymbolAddress((void**)&ppool, g_pool);

    __half* pbh  = (__half*)(ppool + kOffBh);
    __half* pahi = (__half*)(ppool + kOffAhi);
    __half* palo = (__half*)(ppool + kOffAlo);

    cudaFuncSetAttribute((const void*)hgemm_fused<0,2>, cudaFuncAttributeMaxDynamicSharedMemorySize, kGemmSmem);
    cudaFuncSetAttribute((const void*)hgemm_fused<1,2>, cudaFuncAttributeMaxDynamicSharedMemorySize, kGemmSmem);
    cudaFuncSetAttribute((const void*)hgemm_fused<2,2>, cudaFuncAttributeMaxDynamicSharedMemorySize, kGemmSmem);
    cudaFuncSetAttribute((const void*)hgemm_fused<0,1>, cudaFuncAttributeMaxDynamicSharedMemorySize, kGemmSmem);
    cudaFuncSetAttribute((const void*)flash_attn_kernel, cudaFuncAttributeMaxDynamicSharedMemorySize, kAttnSmem);

    dim3 t328(32, 8);
    constexpr int kMB = (kROWS + 127) / 128;   // 32 m-blocks

    // 1. positional encoding + embedding
    pe_kernel<<<1, 1024>>>();
    embed_kernel<<<kROWS, 256>>>(tok, emb);

    // 2. repack per-head QKV weights into [HID, HID] fp32
    pack_w_kernel<<<(kHID * kHID + 255) / 256, 256>>>(Wq, pwq);
    pack_w_kernel<<<(kHID * kHID + 255) / 256, 256>>>(Wk, pwk);
    pack_w_kernel<<<(kHID * kHID + 255) / 256, 256>>>(Wv, pwv);

    // 3. QKV projections on tensor cores (fp16 2-term), scatter epilogue
    split4_kernel<<<(kROWS * kHID / 4 + 255) / 256, 256>>>(px, pahi, palo, kROWS * kHID / 4);
    dim3 gQ(kMB, kHID / 128);
    splitT_kernel<<<dim3(kHID / 32, kHID / 32), t328>>>(pwq, pbh, kHID, kHID);
    hgemm_fused<2,2><<<gQ, 256, kGemmSmem>>>(pahi, palo, pbh, bq, pq, kROWS, kHID, kHID);
    splitT_kernel<<<dim3(kHID / 32, kHID / 32), t328>>>(pwk, pbh, kHID, kHID);
    hgemm_fused<2,2><<<gQ, 256, kGemmSmem>>>(pahi, palo, pbh, bk, pk, kROWS, kHID, kHID);
    splitT_kernel<<<dim3(kHID / 32, kHID / 32), t328>>>(pwv, pbh, kHID, kHID);
    hgemm_fused<2,2><<<gQ, 256, kGemmSmem>>>(pahi, palo, pbh, bv, pv, kROWS, kHID, kHID);

    // 4. fused flash attention (fp32 — protects floor() discontinuity)
    flash_attn_kernel<<<dim3(16, kBH), 256, kAttnSmem>>>();

    // 5. output projection + residual + LN1
    split4_kernel<<<(kROWS * kHID / 4 + 255) / 256, 256>>>(pattn, pahi, palo, kROWS * kHID / 4);
    splitT_kernel<<<dim3(kHID / 32, kHID / 32), t328>>>(Wc, pbh, kHID, kHID);
    hgemm_fused<0,2><<<dim3(kMB, kHID / 128), 256, kGemmSmem>>>(pahi, palo, pbh, bc, pff, kROWS, kHID, kHID);
    add_ln_kernel<<<kROWS, 256>>>(px, pff, ln1g, ln1b, px1);

    // 6. feed-forward + residual + LN2
    split4_kernel<<<(kROWS * kHID / 4 + 255) / 256, 256>>>(px1, pahi, palo, kROWS * kHID / 4);
    splitT_kernel<<<dim3(kFFH / 32, kHID / 32), t328>>>(W1, pbh, kHID, kFFH);
    hgemm_fused<1,2><<<dim3(kMB, kFFH / 128), 256, kGemmSmem>>>(pahi, palo, pbh, b1, ph, kROWS, kFFH, kHID);
    split4_kernel<<<(kROWS * kFFH / 4 + 255) / 256, 256>>>(ph, pahi, palo, kROWS * kFFH / 4);
    splitT_kernel<<<dim3(kHID / 32, kFFH / 32), t328>>>(W2, pbh, kFFH, kHID);
    hgemm_fused<0,2><<<dim3(kMB, kHID / 128), 256, kGemmSmem>>>(pahi, palo, pbh, b2, pff, kROWS, kHID, kFFH);
    add_ln_kernel<<<kROWS, 256>>>(px1, pff, ln2g, ln2b, px2);

    // 7. logits (dominant GEMM) — 1-term fp16: error adds ~2e-4, direct to output
    split4_kernel<<<(kROWS * kHID / 4 + 255) / 256, 256>>>(px2, pahi, palo, kROWS * kHID / 4);
    splitT_kernel<<<dim3(kVOC / 32, kHID / 32), t328>>>(Wlog, pbh, kHID, kVOC);
    hgemm_fused<0,1><<<dim3(kMB, kVOC / 128), 256, kGemmSmem>>>(pahi, palo, pbh, blog, out, kROWS, kVOC, kHID);

    (void)in_sizes; (void)n_in; (void)out_size;
}

// round 16
// speedup vs baseline: 1.9704x; 1.0776x over previous
#include <cuda_runtime.h>
#include <cuda_fp16.h>
#include <math.h>
#include <stdint.h>

// ---------------- problem constants ----------------
constexpr int kB    = 4;
constexpr int kS    = 1000;
constexpr int kHID  = 1024;
constexpr int kNH   = 16;
constexpr int kDK   = 64;
constexpr int kFFH  = 2048;
constexpr int kVOC  = 32000;
constexpr int kROWS = kB * kS;     // 4000
constexpr int kBH   = kB * kNH;    // 64

// ---------------- device scratch (no allocations allowed) ----------------
__device__ float g_pe[kHID];
__device__ float g_x   [kROWS * kHID];
__device__ float g_q   [kBH * kS * kDK];
__device__ float g_k   [kBH * kS * kDK];
__device__ float g_v   [kBH * kS * kDK];
__device__ float g_x1  [kROWS * kHID];
__device__ float g_ff  [kROWS * kHID];
__device__ float g_wq  [kHID * kHID];
__device__ float g_wk  [kHID * kHID];
__device__ float g_wv  [kHID * kHID];

// fp16 pool: B | A0 | A1  (A slots ping-pong; each sized kROWS*kFFH)
constexpr size_t kOffBh = 0;
constexpr size_t kOffA0 = (size_t)kHID * kVOC * 2;
constexpr size_t kOffA1 = kOffA0 + (size_t)kROWS * kFFH * 2;
constexpr size_t kPoolSz = kOffA1 + (size_t)kROWS * kFFH * 2;
__device__ __align__(256) char g_pool[kPoolSz];

// ---------------- positional encoding (source-bug constant vector) ----------------
__global__ void pe_kernel() {
    int c = threadIdx.x;                     // 0..1023
    int i = c & ~1;
    double tmp = 999.0 * exp(-(double)i / 1024.0 * log(10000.0));
    g_pe[c] = (c & 1) ? (float)cos(tmp) : (float)sin(tmp);
}

// x[row] = emb[token[row]] + pe; also emits fp16 hi/lo split for QKV GEMMs
__global__ void embed_kernel(const int* __restrict__ tok, const float* __restrict__ emb,
                             __half* __restrict__ hi, __half* __restrict__ lo) {
    int row = blockIdx.x;
    int t = tok[row];
    const float4* e = (const float4*)(emb + (size_t)t * kHID);
    const float4* p = (const float4*)g_pe;
    float4* xo = (float4*)(g_x + (size_t)row * kHID);
    int c = threadIdx.x;                     // 256 float4 per row
    float4 a = e[c], b = p[c];
    float4 v = make_float4(a.x + b.x, a.y + b.y, a.z + b.z, a.w + b.w);
    xo[c] = v;
    __half h0 = __float2half_rn(v.x), h1 = __float2half_rn(v.y);
    __half h2 = __float2half_rn(v.z), h3 = __float2half_rn(v.w);
    __half2* hp = (__half2*)(hi + (size_t)row * kHID);
    __half2* lp = (__half2*)(lo + (size_t)row * kHID);
    hp[c*2+0] = __halves2half2(h0, h1);
    hp[c*2+1] = __halves2half2(h2, h3);
    lp[c*2+0] = __halves2half2(__float2half_rn(v.x - __half2float(h0)),
                               __float2half_rn(v.y - __half2float(h1)));
    lp[c*2+1] = __halves2half2(__float2half_rn(v.z - __half2float(h2)),
                               __float2half_rn(v.w - __half2float(h3)));
}

// repack W[n][h][d] -> Wp[h][n*64+d]
__global__ void pack_w_kernel(const float* __restrict__ W, float* __restrict__ out) {
    int idx = blockIdx.x * blockDim.x + threadIdx.x;
    if (idx < kHID * kHID) {
        int h = idx >> 10;
        int col = idx & 1023;
        int n = col >> 6, d = col & 63;
        out[idx] = W[((size_t)n * kHID + h) * kDK + d];
    }
}

// ---------------- fp32 [K,N] -> fp16 [N,K] (transpose + round) ----------------
__global__ void splitT_kernel(const float* __restrict__ in,
                              __half* __restrict__ hi, int K, int N) {
    __shared__ float t[32][33];
    int n0 = blockIdx.x * 32, k0 = blockIdx.y * 32;
    int tx = threadIdx.x;
#pragma unroll
    for (int i = threadIdx.y; i < 32; i += 8)
        t[i][tx] = in[(size_t)(k0 + i) * N + n0 + tx];
    __syncthreads();
#pragma unroll
    for (int i = threadIdx.y; i < 32; i += 8)
        hi[(size_t)(n0 + i) * K + k0 + tx] = __float2half_rn(t[tx][i]);
}

// ---------------- cp.async helpers ----------------
__device__ __forceinline__ void cp16(uint32_t dst, const void* src, bool full) {
    int sz = full ? 16 : 0;
    asm volatile("cp.async.cg.shared.global [%0], [%1], 16, %2;"
                 :: "r"(dst), "l"(src), "r"(sz) : "memory");
}
__device__ __forceinline__ void cp_commit() {
    asm volatile("cp.async.commit_group;" ::: "memory");
}

// ---------------- fused fp16 tensor-core GEMM ----------------
// TERMS=2: C = (Ahi+Alo)@B^T + bias; TERMS=1: C = Ahi@B^T + bias.
// EPI: 0 = fp32 plain, 2 = fp32 qkv-scatter, 3 = relu -> fp16 out.
constexpr int kPITCH = 40;
constexpr int kArrSz = 128 * kPITCH;
constexpr int kGemmSmem = 2 * 3 * kArrSz * 2;   // 61440 B

template<int EPI, int TERMS>
__global__ __launch_bounds__(256)
void hgemm_fused(const __half* __restrict__ aHi, const __half* __restrict__ aLo,
                 const __half* __restrict__ Bm,
                 const float* __restrict__ bias, void* __restrict__ Cv,
                 int M, int N, int K) {
    extern __shared__ __align__(16) __half dynsm[];
    uint32_t smbase;
    { uint64_t t64; asm("cvta.to.shared.u64 %0, %1;" : "=l"(t64) : "l"(dynsm)); smbase = (uint32_t)t64; }

    int tid = threadIdx.x;
    int wid = tid >> 5, lane = tid & 31;
    int wm = wid >> 2, wn = wid & 3;          // 2x4 warps -> warp tile 64(m) x 32(n)
    int r = lane >> 2, c2 = (lane & 3) * 2;
    int m0 = blockIdx.x * 128, n0 = blockIdx.y * 128;

    const __half* gsrc[3] = {aHi, aLo, Bm};

    auto issue_tile = [&](int stage, int k0) {
#pragma unroll
        for (int arr = 0; arr < 3; arr++) {
            if (TERMS == 1 && arr == 1) continue;
            const __half* gp = gsrc[arr];
            bool isA = arr < 2;
#pragma unroll
            for (int i = 0; i < 2; i++) {
                int idx = tid + i * 256;
                int row = idx >> 2;
                int c4 = (idx & 3) * 8;
                int grow = (isA ? m0 : n0) + row;
                bool ok = isA ? (grow < M) : true;
                const void* src = gp + (size_t)(ok ? grow : 0) * K + k0 + c4;
                uint32_t dst = smbase + (uint32_t)(((stage * 3 + arr) * kArrSz + row * kPITCH + c4) * 2);
                cp16(dst, src, ok);
            }
        }
    };

    float acc[4][4][4] = {};

    issue_tile(0, 0);
    cp_commit();

    int stage = 0;
    for (int k0 = 0; k0 < K; k0 += 32) {
        bool hasNext = (k0 + 32) < K;
        if (hasNext) {
            issue_tile(stage ^ 1, k0 + 32);
            cp_commit();
            asm volatile("cp.async.wait_group 1;" ::: "memory");
        } else {
            asm volatile("cp.async.wait_group 0;" ::: "memory");
        }
        __syncthreads();

        const __half* sAhi = dynsm + (stage * 3 + 0) * kArrSz;
        const __half* sAlo = dynsm + (stage * 3 + 1) * kArrSz;
        const __half* sB   = dynsm + (stage * 3 + 2) * kArrSz;

#pragma unroll
        for (int ks = 0; ks < 32; ks += 16) {
            uint32_t ahi[4][4], alo[4][4], bfr[4][2];
#pragma unroll
            for (int mi = 0; mi < 4; mi++) {
                int rr = (wm * 64 + mi * 16 + r) * kPITCH + ks + c2;
                ahi[mi][0] = *(const uint32_t*)&sAhi[rr];
                ahi[mi][1] = *(const uint32_t*)&sAhi[rr + 8 * kPITCH];
                ahi[mi][2] = *(const uint32_t*)&sAhi[rr + 8];
                ahi[mi][3] = *(const uint32_t*)&sAhi[rr + 8 * kPITCH + 8];
                if (TERMS == 2) {
                    alo[mi][0] = *(const uint32_t*)&sAlo[rr];
                    alo[mi][1] = *(const uint32_t*)&sAlo[rr + 8 * kPITCH];
                    alo[mi][2] = *(const uint32_t*)&sAlo[rr + 8];
                    alo[mi][3] = *(const uint32_t*)&sAlo[rr + 8 * kPITCH + 8];
                }
            }
#pragma unroll
            for (int ni = 0; ni < 4; ni++) {
                int rr = (wn * 32 + ni * 8 + r) * kPITCH + ks + c2;
                bfr[ni][0] = *(const uint32_t*)&sB[rr];
                bfr[ni][1] = *(const uint32_t*)&sB[rr + 8];
            }
#define MMA(A0,A1,A2,A3,B0,B1,ACC) \
    asm volatile("mma.sync.aligned.m16n8k16.row.col.f32.f16.f16.f32 " \
                 "{%0,%1,%2,%3}, {%4,%5,%6,%7}, {%8,%9}, {%0,%1,%2,%3};" \
                 : "+f"(ACC[0]), "+f"(ACC[1]), "+f"(ACC[2]), "+f"(ACC[3]) \
                 : "r"(A0), "r"(A1), "r"(A2), "r"(A3), "r"(B0), "r"(B1))
#pragma unroll
            for (int mi = 0; mi < 4; mi++)
#pragma unroll
                for (int ni = 0; ni < 4; ni++) {
                    MMA(ahi[mi][0], ahi[mi][1], ahi[mi][2], ahi[mi][3],
                        bfr[ni][0], bfr[ni][1], acc[mi][ni]);
                    if (TERMS == 2)
                        MMA(alo[mi][0], alo[mi][1], alo[mi][2], alo[mi][3],
                            bfr[ni][0], bfr[ni][1], acc[mi][ni]);
                }
#undef MMA
        }
        __syncthreads();
        stage ^= 1;
    }

#pragma unroll
    for (int mi = 0; mi < 4; mi++) {
#pragma unroll
        for (int half = 0; half < 2; half++) {
            int row = m0 + wm * 64 + mi * 16 + r + half * 8;
            if (row >= M) continue;
#pragma unroll
            for (int ni = 0; ni < 4; ni++) {
                int col = n0 + wn * 32 + ni * 8 + c2;
                float v0 = acc[mi][ni][half * 2 + 0] + bias[col];
                float v1 = acc[mi][ni][half * 2 + 1] + bias[col + 1];
                if (EPI == 3) {
                    v0 = fmaxf(v0, 0.f); v1 = fmaxf(v1, 0.f);
                    __half2* Ch = (__half2*)((__half*)Cv + (size_t)row * N + col);
                    *Ch = __halves2half2(__float2half_rn(v0), __float2half_rn(v1));
                } else if (EPI == 2) {
                    float* C = (float*)Cv;
                    int b = row / kS, s = row % kS;
                    int n = col >> 6, d = col & 63;
                    size_t base = (((size_t)(b * kNH + n)) * kS + s) * kDK + d;
                    C[base] = v0; C[base + 1] = v1;
                } else {
                    *(float2*)((float*)Cv + (size_t)row * N + col) = make_float2(v0, v1);
                }
            }
        }
    }
}

// ---------------- fused flash attention (writes fp16 attn for 1-term Wc) ----------------
constexpr int kAttnSmem = 4 * 64 * 68 * 4;

__global__ __launch_bounds__(256)
void flash_attn_kernel(__half* __restrict__ attn_h) {
    extern __shared__ float asm_[];
    float (*Ks)[68] = (float(*)[68])asm_;
    float (*Qs)[68] = (float(*)[68])(asm_ + 64 * 68);
    float (*Vs)[68] = (float(*)[68])(asm_ + 2 * 64 * 68);
    float (*Ps)[68] = (float(*)[68])(asm_ + 3 * 64 * 68);

    int bh = blockIdx.y;
    int s0 = blockIdx.x * 64;
    const float* kp = g_k + (size_t)bh * kS * kDK;
    const float* qp = g_q + (size_t)bh * kS * kDK;
    const float* vp = g_v + (size_t)bh * kS * kDK;
    int tid = threadIdx.x;
    int tr = tid >> 4, tc = tid & 15;

#pragma unroll
    for (int i = 0; i < 4; i++) {
        int idx = tid + i * 256;
        int r = idx >> 4;
        int c = (idx & 15) << 2;
        float4 vk = (s0 + r < kS) ? *(const float4*)&kp[(size_t)(s0 + r) * kDK + c]
                                  : make_float4(0.f, 0.f, 0.f, 0.f);
        Ks[c + 0][r] = vk.x; Ks[c + 1][r] = vk.y; Ks[c + 2][r] = vk.z; Ks[c + 3][r] = vk.w;
    }

    float m_run[4], l_run[4], acc[4][4];
#pragma unroll
    for (int i = 0; i < 4; i++) {
        m_run[i] = -1e30f; l_run[i] = 0.f;
#pragma unroll
        for (int j = 0; j < 4; j++) acc[i][j] = 0.f;
    }

    for (int t0 = 0; t0 <= s0; t0 += 64) {
        __syncthreads();
#pragma unroll
        for (int i = 0; i < 4; i++) {
            int idx = tid + i * 256;
            int r = idx >> 4;
            int c = (idx & 15) << 2;
            bool ok = (t0 + r < kS);
            float4 vq = ok ? *(const float4*)&qp[(size_t)(t0 + r) * kDK + c]
                           : make_float4(0.f, 0.f, 0.f, 0.f);
            Qs[c + 0][r] = vq.x; Qs[c + 1][r] = vq.y; Qs[c + 2][r] = vq.z; Qs[c + 3][r] = vq.w;
            float4 vv = ok ? *(const float4*)&vp[(size_t)(t0 + r) * kDK + c]
                           : make_float4(0.f, 0.f, 0.f, 0.f);
            *(float4*)&Vs[r][c] = vv;
        }
        __syncthreads();

        float S[4][4] = {};
#pragma unroll
        for (int d = 0; d < 64; d++) {
            float ra[4], rb[4];
#pragma unroll
            for (int i = 0; i < 4; i++) ra[i] = Ks[d][tr * 4 + i];
#pragma unroll
            for (int j = 0; j < 4; j++) rb[j] = Qs[d][tc * 4 + j];
#pragma unroll
            for (int i = 0; i < 4; i++)
#pragma unroll
                for (int j = 0; j < 4; j++) S[i][j] += ra[i] * rb[j];
        }
#pragma unroll
        for (int i = 0; i < 4; i++) {
            int s = s0 + tr * 4 + i;
#pragma unroll
            for (int j = 0; j < 4; j++) {
                int t = t0 + tc * 4 + j;
                S[i][j] = (t > s) ? -INFINITY : floorf(S[i][j] * 0.125f);
            }
        }
        float corr[4];
#pragma unroll
        for (int i = 0; i < 4; i++) {
            float mt = fmaxf(fmaxf(S[i][0], S[i][1]), fmaxf(S[i][2], S[i][3]));
#pragma unroll
            for (int o = 8; o; o >>= 1) mt = fmaxf(mt, __shfl_xor_sync(0xffffffffu, mt, o, 16));
            float nm = fmaxf(m_run[i], mt);
            corr[i] = expf(m_run[i] - nm);
            m_run[i] = nm;
            float ls = 0.f;
#pragma unroll
            for (int j = 0; j < 4; j++) {
                float p = expf(S[i][j] - nm);
                S[i][j] = p;
                ls += p;
            }
#pragma unroll
            for (int o = 8; o; o >>= 1) ls += __shfl_xor_sync(0xffffffffu, ls, o, 16);
            l_run[i] = l_run[i] * corr[i] + ls;
#pragma unroll
            for (int j = 0; j < 4; j++) acc[i][j] *= corr[i];
        }
#pragma unroll
        for (int i = 0; i < 4; i++)
#pragma unroll
            for (int j = 0; j < 4; j++)
                Ps[tc * 4 + j][tr * 4 + i] = S[i][j];
        __syncthreads();

#pragma unroll
        for (int k = 0; k < 64; k++) {
            float ra[4], rb[4];
#pragma unroll
            for (int i = 0; i < 4; i++) ra[i] = Ps[k][tr * 4 + i];
#pragma unroll
            for (int j = 0; j < 4; j++) rb[j] = Vs[k][tc * 4 + j];
#pragma unroll
            for (int i = 0; i < 4; i++)
#pragma unroll
                for (int j = 0; j < 4; j++) acc[i][j] += ra[i] * rb[j];
        }
    }

    int b = bh >> 4, n = bh & 15;
#pragma unroll
    for (int i = 0; i < 4; i++) {
        int s = s0 + tr * 4 + i;
        if (s >= kS) continue;
        float inv = 1.f / l_run[i];
        __half2* op = (__half2*)(attn_h + ((size_t)(b * kS + s)) * kHID + n * kDK + tc * 4);
        op[0] = __halves2half2(__float2half_rn(acc[i][0] * inv), __float2half_rn(acc[i][1] * inv));
        op[1] = __halves2half2(__float2half_rn(acc[i][2] * inv), __float2half_rn(acc[i][3] * inv));
    }
}

// ---------------- LayerNorm(x + delta): MODE 1 = fp32 + fp16 out, 2 = fp16 only ----------------
template<int MODE>
__global__ __launch_bounds__(256)
void add_ln_kernel(const float* __restrict__ xin, const float* __restrict__ dl,
                   const float* __restrict__ g, const float* __restrict__ b,
                   float* __restrict__ out32, __half* __restrict__ out16) {
    int row = blockIdx.x;
    int tid = threadIdx.x;
    const float* xr = xin + (size_t)row * kHID;
    const float* dr = dl  + (size_t)row * kHID;
    __shared__ float red[256];

    float v[4]; float ls = 0.f;
#pragma unroll
    for (int i = 0; i < 4; i++) { int c = tid + i * 256; v[i] = xr[c] + dr[c]; ls += v[i]; }
    red[tid] = ls; __syncthreads();
    for (int o = 128; o; o >>= 1) { if (tid < o) red[tid] += red[tid + o]; __syncthreads(); }
    float mu = red[0] * (1.f / kHID);
    __syncthreads();

    float lv = 0.f;
#pragma unroll
    for (int i = 0; i < 4; i++) { float d = v[i] - mu; lv += d * d; }
    red[tid] = lv; __syncthreads();
    for (int o = 128; o; o >>= 1) { if (tid < o) red[tid] += red[tid + o]; __syncthreads(); }
    float rstd = 1.f / sqrtf(red[0] * (1.f / kHID) + 1e-5f);

#pragma unroll
    for (int i = 0; i < 4; i++) {
        int c = tid + i * 256;
        float o = (v[i] - mu) * rstd * g[c] + b[c];
        if (MODE == 1) out32[(size_t)row * kHID + c] = o;
        out16[(size_t)row * kHID + c] = __float2half_rn(o);
    }
}

// ---------------- launcher ----------------
extern "C" void kernel_launch(void* const* d_in, const int* in_sizes, int n_in,
                              void* d_out, int out_size) {
    const int*   tok  = (const int*)  d_in[0];
    const float* emb  = (const float*)d_in[1];
    const float* Wq   = (const float*)d_in[2];
    const float* bq   = (const float*)d_in[3];
    const float* Wk   = (const float*)d_in[4];
    const float* bk   = (const float*)d_in[5];
    const float* Wv   = (const float*)d_in[6];
    const float* bv   = (const float*)d_in[7];
    const float* Wc   = (const float*)d_in[8];
    const float* bc   = (const float*)d_in[9];
    const float* ln1g = (const float*)d_in[10];
    const float* ln1b = (const float*)d_in[11];
    const float* W1   = (const float*)d_in[12];
    const float* b1   = (const float*)d_in[13];
    const float* W2   = (const float*)d_in[14];
    const float* b2   = (const float*)d_in[15];
    const float* ln2g = (const float*)d_in[16];
    const float* ln2b = (const float*)d_in[17];
    const float* Wlog = (const float*)d_in[18];
    const float* blog = (const float*)d_in[19];
    float* out = (float*)d_out;

    float *px, *pq, *pk, *pv, *px1, *pff, *pwq, *pwk, *pwv;
    char* ppool;
    cudaGetSymbolAddress((void**)&px,    g_x);
    cudaGetSymbolAddress((void**)&pq,    g_q);
    cudaGetSymbolAddress((void**)&pk,    g_k);
    cudaGetSymbolAddress((void**)&pv,    g_v);
    cudaGetSymbolAddress((void**)&px1,   g_x1);
    cudaGetSymbolAddress((void**)&pff,   g_ff);
    cudaGetSymbolAddress((void**)&pwq,   g_wq);
    cudaGetSymbolAddress((void**)&pwk,   g_wk);
    cudaGetSymbolAddress((void**)&pwv,   g_wv);
    cudaGetSymbolAddress((void**)&ppool, g_pool);

    __half* pbh = (__half*)(ppool + kOffBh);
    __half* pA0 = (__half*)(ppool + kOffA0);
    __half* pA1 = (__half*)(ppool + kOffA1);

    cudaFuncSetAttribute((const void*)hgemm_fused<0,1>, cudaFuncAttributeMaxDynamicSharedMemorySize, kGemmSmem);
    cudaFuncSetAttribute((const void*)hgemm_fused<2,2>, cudaFuncAttributeMaxDynamicSharedMemorySize, kGemmSmem);
    cudaFuncSetAttribute((const void*)hgemm_fused<3,1>, cudaFuncAttributeMaxDynamicSharedMemorySize, kGemmSmem);
    cudaFuncSetAttribute((const void*)flash_attn_kernel, cudaFuncAttributeMaxDynamicSharedMemorySize, kAttnSmem);

    dim3 t328(32, 8);
    constexpr int kMB = (kROWS + 127) / 128;   // 32 m-blocks

    // 1. positional encoding + embedding (emits x fp32 + hi/lo fp16)
    pe_kernel<<<1, 1024>>>();
    embed_kernel<<<kROWS, 256>>>(tok, emb, pA0, pA1);

    // 2. repack per-head QKV weights into [HID, HID] fp32
    pack_w_kernel<<<(kHID * kHID + 255) / 256, 256>>>(Wq, pwq);
    pack_w_kernel<<<(kHID * kHID + 255) / 256, 256>>>(Wk, pwk);
    pack_w_kernel<<<(kHID * kHID + 255) / 256, 256>>>(Wv, pwv);

    // 3. QKV projections (2-term — protects floor() path), scatter epilogue
    dim3 gQ(kMB, kHID / 128);
    splitT_kernel<<<dim3(kHID / 32, kHID / 32), t328>>>(pwq, pbh, kHID, kHID);
    hgemm_fused<2,2><<<gQ, 256, kGemmSmem>>>(pA0, pA1, pbh, bq, pq, kROWS, kHID, kHID);
    splitT_kernel<<<dim3(kHID / 32, kHID / 32), t328>>>(pwk, pbh, kHID, kHID);
    hgemm_fused<2,2><<<gQ, 256, kGemmSmem>>>(pA0, pA1, pbh, bk, pk, kROWS, kHID, kHID);
    splitT_kernel<<<dim3(kHID / 32, kHID / 32), t328>>>(pwv, pbh, kHID, kHID);
    hgemm_fused<2,2><<<gQ, 256, kGemmSmem>>>(pA0, pA1, pbh, bv, pv, kROWS, kHID, kHID);

    // 4. fused flash attention (fp32 math) -> fp16 attn in pA0 (x hi/lo now dead)
    flash_attn_kernel<<<dim3(16, kBH), 256, kAttnSmem>>>(pA0);

    // 5. output projection (1-term) + residual + LN1 (emits x1 fp32 + fp16 in pA1)
    splitT_kernel<<<dim3(kHID / 32, kHID / 32), t328>>>(Wc, pbh, kHID, kHID);
    hgemm_fused<0,1><<<dim3(kMB, kHID / 128), 256, kGemmSmem>>>(pA0, pA0, pbh, bc, pff, kROWS, kHID, kHID);
    add_ln_kernel<1><<<kROWS, 256>>>(px, pff, ln1g, ln1b, px1, pA1);

    // 6. feed-forward (1-term; FF1 epilogue emits fp16 relu to pA0) + residual + LN2
    splitT_kernel<<<dim3(kFFH / 32, kHID / 32), t328>>>(W1, pbh, kHID, kFFH);
    hgemm_fused<3,1><<<dim3(kMB, kFFH / 128), 256, kGemmSmem>>>(pA1, pA1, pbh, b1, pA0, kROWS, kFFH, kHID);
    splitT_kernel<<<dim3(kHID / 32, kFFH / 32), t328>>>(W2, pbh, kFFH, kHID);
    hgemm_fused<0,1><<<dim3(kMB, kHID / 128), 256, kGemmSmem>>>(pA0, pA0, pbh, b2, pff, kROWS, kHID, kFFH);
    add_ln_kernel<2><<<kROWS, 256>>>(px1, pff, ln2g, ln2b, nullptr, pA1);

    // 7. logits (1-term) -> d_out
    splitT_kernel<<<dim3(kVOC / 32, kHID / 32), t328>>>(Wlog, pbh, kHID, kVOC);
    hgemm_fused<0,1><<<dim3(kMB, kVOC / 128), 256, kGemmSmem>>>(pA1, pA1, pbh, blog, out, kROWS, kVOC, kHID);

    (void)in_sizes; (void)n_in; (void)out_size;
}